// round 12
// baseline (speedup 1.0000x reference)
#include <cuda_runtime.h>
#include <cuda_fp16.h>
#include <cstdint>
#include <cstddef>

// ---------------------------------------------------------------------------
// Problem constants
// ---------------------------------------------------------------------------
constexpr int B_  = 4;
constexpr int T_  = 2048;
constexpr int D_  = 1024;
constexpr int H_  = 16;
constexpr int HD_ = 64;
constexpr int M_  = B_ * T_;   // 8192

// 0.125 * log2(e): folded into Q so softmax uses exp2
constexpr float QSCALE = 0.18033688011112042f;

// ---------------------------------------------------------------------------
// Device scratch (pure f16 pipeline, fp32 accumulation in-kernel)
// ---------------------------------------------------------------------------
__device__ __align__(128) __half g_x16[(size_t)M_ * D_];   // x f16
__device__ __align__(128) __half g_o16[(size_t)M_ * D_];   // attnO f16 [B*T, D]
__device__ __align__(128) __half g_q16[(size_t)M_ * D_];   // [B,H,T,HD]
__device__ __align__(128) __half g_k16[(size_t)M_ * D_];
__device__ __align__(128) __half g_v16[(size_t)M_ * D_];
// 4 weights transposed to [N, K] f16, z: 0..3 -> wq,wk,wv,wo
__device__ __align__(128) __half g_wt[(size_t)4 * D_ * D_];
// persistent-GEMM tile counters (reset by wquant each call)
__device__ unsigned int g_ctr[2];

// ---------------------------------------------------------------------------
// PTX helpers
// ---------------------------------------------------------------------------
__device__ __forceinline__ uint32_t smem_u32(const void* p) {
    uint32_t a;
    asm("{ .reg .u64 t; cvta.to.shared.u64 t, %1; cvt.u32.u64 %0, t; }"
        : "=r"(a) : "l"(p));
    return a;
}
__device__ __forceinline__ void cp16(uint32_t saddr, const void* gaddr) {
    asm volatile("cp.async.cg.shared.global [%0], [%1], 16;"
                 :: "r"(saddr), "l"(gaddr));
}
__device__ __forceinline__ void cp_commit() {
    asm volatile("cp.async.commit_group;");
}
template <int N>
__device__ __forceinline__ void cp_wait() {
    asm volatile("cp.async.wait_group %0;" :: "n"(N));
}
__device__ __forceinline__ void ldm_x4(uint32_t* r, uint32_t addr) {
    asm volatile("ldmatrix.sync.aligned.m8n8.x4.shared.b16 {%0,%1,%2,%3}, [%4];"
                 : "=r"(r[0]), "=r"(r[1]), "=r"(r[2]), "=r"(r[3]) : "r"(addr));
}
__device__ __forceinline__ void ldm_x4_t(uint32_t* r, uint32_t addr) {
    asm volatile("ldmatrix.sync.aligned.m8n8.x4.trans.shared.b16 {%0,%1,%2,%3}, [%4];"
                 : "=r"(r[0]), "=r"(r[1]), "=r"(r[2]), "=r"(r[3]) : "r"(addr));
}
__device__ __forceinline__ void mma_f16(float* c, const uint32_t* a,
                                        const uint32_t* b) {
    asm volatile(
        "mma.sync.aligned.m16n8k16.row.col.f32.f16.f16.f32 "
        "{%0,%1,%2,%3}, {%4,%5,%6,%7}, {%8,%9}, {%0,%1,%2,%3};"
        : "+f"(c[0]), "+f"(c[1]), "+f"(c[2]), "+f"(c[3])
        : "r"(a[0]), "r"(a[1]), "r"(a[2]), "r"(a[3]), "r"(b[0]), "r"(b[1]));
}
__device__ __forceinline__ float ex2f(float x) {
    float r;
    asm("ex2.approx.ftz.f32 %0, %1;" : "=f"(r) : "f"(x));
    return r;
}
// packed f16x2: {low=lo, high=hi}
__device__ __forceinline__ uint32_t packh2(float lo, float hi) {
    uint32_t r;
    asm("cvt.rn.f16x2.f32 %0, %1, %2;" : "=r"(r) : "f"(hi), "f"(lo));
    return r;
}
__device__ __forceinline__ uint32_t ex2h2(uint32_t x) {
    uint32_t r;
    asm("ex2.approx.f16x2 %0, %1;" : "=r"(r) : "r"(x));
    return r;
}

// ---------------------------------------------------------------------------
// Persistent HMMA GEMM, 1-term f16: C = A16 @ W16^T + bias, fp32 accum.
// grid = 296 CTAs (2/SM), atomic tile counter; per tile: 8 warps (4Mx2N),
// warp 32x64, BK=32, 6-stage cp.async ring, single sync per kt.
// MODE 0: tiles z in {0,1,2} -> q/k/v f16 [B,H,T,HD]; Q pre-scaled.
// MODE 1: z = 3 -> out fp32 [M, D].
// ---------------------------------------------------------------------------
constexpr int BK        = 32;
constexpr int G_ARR_B   = 128 * 64;                   // 8192 B per tile array
constexpr int G_STAGE_B = 2 * G_ARR_B;                // 16384 (A, W)
constexpr int G_NSTG    = 6;
constexpr int GEMM_SMEM = G_NSTG * G_STAGE_B + 128;   // ring + control slot
constexpr int KT_G      = D_ / BK;                    // 32
constexpr int GEMM_GRID = 296;

__device__ __forceinline__ uint32_t gswz(int row, int chunk) {
    return (uint32_t)row * 64u + (uint32_t)((chunk ^ ((row >> 1) & 3)) << 4);
}

template <int MODE>
__global__ __launch_bounds__(256, 2)
void gemm_mma(const __half* __restrict__ A,
              const float* __restrict__ b0, const float* __restrict__ b1,
              const float* __restrict__ b2,
              float* __restrict__ out)
{
    extern __shared__ __align__(128) char smem[];
    const uint32_t sb = smem_u32(smem);
    int* tileSlot = reinterpret_cast<int*>(smem + G_NSTG * G_STAGE_B);

    constexpr int NT = (MODE == 0) ? 1536 : 512;

    const int tid  = threadIdx.x;
    const int wid  = tid >> 5;
    const int lane = tid & 31;
    const int wm   = (wid & 3) * 32;
    const int wn   = (wid >> 2) * 64;

    const int c0r = tid >> 2,         c0q = tid & 3;
    const int c1r = (tid + 256) >> 2, c1q = (tid + 256) & 3;
    const uint32_t s0 = gswz(c0r, c0q), s1 = gswz(c1r, c1q);

    int rowA[2], rowB[4];
    #pragma unroll
    for (int mi = 0; mi < 2; mi++)
        rowA[mi] = wm + (lane & 7) + ((lane >> 3) & 1) * 8 + mi * 16;
    #pragma unroll
    for (int p = 0; p < 4; p++)
        rowB[p] = wn + ((lane >> 4) & 1) * 8 + (lane & 7) + p * 16;
    const int chA = (lane >> 4) & 1;
    const int chB = (lane >> 3) & 1;

    for (;;) {
        __syncthreads();                   // ring + control safe to reuse
        if (tid == 0)
            *tileSlot = (int)atomicAdd(&g_ctr[MODE], 1u);
        __syncthreads();
        const int tile = *tileSlot;
        if (tile >= NT) break;

        const int z     = (MODE == 0) ? (tile >> 9) : 3;
        const int rem   = tile & 511;
        const int mBase = (rem >> 3) * 128;
        const int nBase = (rem & 7) * 128;
        const __half* W = g_wt + ((size_t)z << 20);

        auto load_stage = [&](int stg, int kt) {
            const uint32_t st = sb + stg * G_STAGE_B;
            const int bk = kt * BK;
            cp16(st + s0, A + (size_t)(mBase + c0r) * D_ + bk + c0q * 8);
            cp16(st + s1, A + (size_t)(mBase + c1r) * D_ + bk + c1q * 8);
            cp16(st + G_ARR_B + s0, W + (size_t)(nBase + c0r) * D_ + bk + c0q * 8);
            cp16(st + G_ARR_B + s1, W + (size_t)(nBase + c1r) * D_ + bk + c1q * 8);
            cp_commit();
        };

        float acc[2][8][4];
        #pragma unroll
        for (int mi = 0; mi < 2; mi++)
            #pragma unroll
            for (int ni = 0; ni < 8; ni++)
                #pragma unroll
                for (int r = 0; r < 4; r++) acc[mi][ni][r] = 0.f;

        #pragma unroll
        for (int j = 0; j < 5; j++) load_stage(j, j);

        #pragma unroll 1
        for (int kt = 0; kt < KT_G; kt++) {
            cp_wait<4>();
            __syncthreads();

            if (kt + 5 < KT_G) load_stage((kt + 5) % G_NSTG, kt + 5);
            else               cp_commit();

            const uint32_t st = sb + (kt % G_NSTG) * G_STAGE_B;
            const uint32_t sA = st;
            const uint32_t sW = st + G_ARR_B;

            #pragma unroll
            for (int ks = 0; ks < 2; ks++) {
                uint32_t af[2][4];
                #pragma unroll
                for (int mi = 0; mi < 2; mi++)
                    ldm_x4(af[mi], sA + gswz(rowA[mi], chA + ks * 2));
                uint32_t bf[4][4];
                #pragma unroll
                for (int p = 0; p < 4; p++)
                    ldm_x4(bf[p], sW + gswz(rowB[p], chB + ks * 2));
                #pragma unroll
                for (int mi = 0; mi < 2; mi++)
                    #pragma unroll
                    for (int p = 0; p < 4; p++)
                        #pragma unroll
                        for (int hf = 0; hf < 2; hf++)
                            mma_f16(acc[mi][p * 2 + hf], af[mi], &bf[p][hf * 2]);
            }
        }
        cp_wait<0>();   // drain tail empty groups before ring reuse next tile

        // --- epilogue ---
        const float* bias;
        __half* dst16 = nullptr;
        float scale = 1.f;
        if (MODE == 0) {
            if (z == 0)      { dst16 = g_q16; bias = b0; scale = QSCALE; }
            else if (z == 1) { dst16 = g_k16; bias = b1; }
            else             { dst16 = g_v16; bias = b2; }
        } else {
            bias = b0;
        }

        #pragma unroll
        for (int mi = 0; mi < 2; mi++) {
            #pragma unroll
            for (int ni = 0; ni < 8; ni++) {
                const int n0 = nBase + wn + ni * 8 + (lane & 3) * 2;
                const float bv0 = __ldg(bias + n0), bv1 = __ldg(bias + n0 + 1);
                #pragma unroll
                for (int rr = 0; rr < 2; rr++) {
                    const int m = mBase + wm + mi * 16 + (lane >> 2) + rr * 8;
                    float v0 = acc[mi][ni][rr * 2 + 0] + bv0;
                    float v1 = acc[mi][ni][rr * 2 + 1] + bv1;
                    if (MODE == 0) {
                        v0 *= scale; v1 *= scale;
                        const int bb = m >> 11, tt = m & 2047;
                        const int hh = n0 >> 6, hd = n0 & 63;
                        const size_t idx =
                            ((((size_t)bb * H_ + hh) * T_ + tt) << 6) + hd;
                        reinterpret_cast<uint32_t*>(dst16)[idx >> 1] =
                            packh2(v0, v1);
                    } else {
                        *reinterpret_cast<float2*>(out + (size_t)m * D_ + n0) =
                            make_float2(v0, v1);
                    }
                }
            }
        }
    }
}

// ---------------------------------------------------------------------------
// Tensor-core causal flash attention, pure f16, fp32 accum, S-prefetch
// software pipelining: S(kt+1) MMAs issued before softmax(kt)+PV(kt) so the
// tensor pipe overlaps the scalar/MUFU softmax. Q persistent in smem;
// 5-stage KV ring (16KB/stage) + 16KB Q region = 96KB, 2 CTAs/SM.
// ---------------------------------------------------------------------------
constexpr int ATT_ARR_B   = 64 * 128;                 // 8192 per array
constexpr int ATT_STAGE_B = 2 * ATT_ARR_B;            // 16384 (k, v)
constexpr int ATT_NSTG    = 5;                        // KV ring stages
constexpr int ATT_SMEM    = (ATT_NSTG + 1) * ATT_STAGE_B;  // + Q region = 98304

__device__ __forceinline__ uint32_t aswz(int row, int chunk) {
    return (uint32_t)row * 128u + (uint32_t)((chunk ^ (row & 7)) << 4);
}

__global__ __launch_bounds__(256, 2)
void attn_mma()
{
    extern __shared__ __align__(128) char smem[];
    const uint32_t sb  = smem_u32(smem);
    const uint32_t qsb = sb + ATT_NSTG * ATT_STAGE_B;   // Q region

    const int tid  = threadIdx.x;
    const int wid  = tid >> 5;
    const int lane = tid & 31;

    const int qb = (gridDim.x - 1) - blockIdx.x;     // largest-first
    const int h  = blockIdx.y, b = blockIdx.z;
    const size_t bh = ((size_t)(b * H_ + h)) * T_ * HD_;

    const __half* Q = g_q16 + bh + (size_t)qb * 128 * HD_;
    const __half* K = g_k16 + bh;
    const __half* V = g_v16 + bh;

    const int KT = 2 * qb + 2;   // always even, >= 2

    // ---- prologue: Q -> Q region; KV stages 0..3 (guarded) ----
    #pragma unroll
    for (int i = 0; i < 4; i++) {
        const int c = i * 256 + tid;
        const int row = c >> 3, q8 = c & 7;
        cp16(qsb + aswz(row, q8), Q + (size_t)row * HD_ + q8 * 8);
    }
    cp_commit();

    auto load_kv = [&](int stg, int kt) {
        const uint32_t base = sb + stg * ATT_STAGE_B;
        #pragma unroll
        for (int i = 0; i < 4; i++) {
            const int c = i * 256 + tid;
            const int arr = c >> 9, row = (c >> 3) & 63, q8 = c & 7;
            const __half* g = arr ? V : K;
            cp16(base + arr * ATT_ARR_B + aswz(row, q8),
                 g + (size_t)(kt * 64 + row) * HD_ + q8 * 8);
        }
        cp_commit();
    };
    #pragma unroll
    for (int j = 0; j < 4; j++) {
        if (j < KT) load_kv(j, j);
        else        cp_commit();
    }

    cp_wait<3>();                // Q + stage 0 ready
    __syncthreads();

    const int rowQ  = wid * 16 + (lane & 7) + ((lane >> 3) & 1) * 8;
    const int chQ   = (lane >> 4) & 1;
    const int rKbase = ((lane >> 4) & 1) * 8 + (lane & 7);
    const int chK    = (lane >> 3) & 1;
    const int rVbase = (lane & 7) + ((lane >> 3) & 1) * 8;
    const int chV    = (lane >> 4) & 1;
    const int r0g = qb * 128 + wid * 16 + (lane >> 2);

    const uint32_t ONES2[2] = {0x3C003C00u, 0x3C003C00u};

    // S = Q . K for key tile in ring slot stK
    auto computeS = [&](float (&s)[8][4], uint32_t stK) {
        #pragma unroll
        for (int nt = 0; nt < 8; nt++)
            #pragma unroll
            for (int r = 0; r < 4; r++) s[nt][r] = 0.f;
        #pragma unroll
        for (int kc = 0; kc < 4; kc++) {
            uint32_t qf[4];
            ldm_x4(qf, qsb + aswz(rowQ, chQ + kc * 2));
            #pragma unroll
            for (int g2 = 0; g2 < 2; g2++) {
                uint32_t kf[2][4];
                #pragma unroll
                for (int t = 0; t < 2; t++)
                    ldm_x4(kf[t], stK + aswz(rKbase + (g2 * 2 + t) * 16,
                                             chK + kc * 2));
                #pragma unroll
                for (int t = 0; t < 2; t++)
                    #pragma unroll
                    for (int hf = 0; hf < 2; hf++)
                        mma_f16(s[(g2 * 2 + t) * 2 + hf], qf, &kf[t][hf * 2]);
            }
        }
    };

    float o[8][4];
    #pragma unroll
    for (int nt = 0; nt < 8; nt++)
        #pragma unroll
        for (int r = 0; r < 4; r++) o[nt][r] = 0.f;
    float m0 = -1e30f, m1 = -1e30f, l0 = 0.f, l1 = 0.f;

    float sA[8][4], sB[8][4];
    computeS(sA, sb);            // S(0) from ring slot 0

    // one pipeline step: softmax+PV on cur (tile kt); prefetch S(kt+1) -> nxt
    auto step = [&](int kt, float (&cur)[8][4], float (&nxt)[8][4]) {
        cp_wait<2>();            // stage kt+1 loaded
        __syncthreads();         // all warps done with stage kt-1
        if (kt + 4 < KT) load_kv((kt + 4) % ATT_NSTG, kt + 4);
        else             cp_commit();

        const uint32_t stV = sb + (kt % ATT_NSTG) * ATT_STAGE_B + ATT_ARR_B;

        // ---- prefetch next S (independent of softmax below) ----
        if (kt + 1 < KT)
            computeS(nxt, sb + ((kt + 1) % ATT_NSTG) * ATT_STAGE_B);

        // ---- causal mask (last two tiles only) ----
        if (kt >= KT - 2) {
            const int colBase = kt * 64 + (lane & 3) * 2;
            #pragma unroll
            for (int nt = 0; nt < 8; nt++)
                #pragma unroll
                for (int j = 0; j < 2; j++) {
                    const int c = colBase + nt * 8 + j;
                    if (c > r0g)     cur[nt][j]     = -30000.f;
                    if (c > r0g + 8) cur[nt][2 + j] = -30000.f;
                }
        }

        // ---- max-reduce + o rescale ----
        float tm0 = -1e30f, tm1 = -1e30f;
        #pragma unroll
        for (int nt = 0; nt < 8; nt++) {
            tm0 = fmaxf(tm0, fmaxf(cur[nt][0], cur[nt][1]));
            tm1 = fmaxf(tm1, fmaxf(cur[nt][2], cur[nt][3]));
        }
        tm0 = fmaxf(tm0, __shfl_xor_sync(0xffffffffu, tm0, 1));
        tm0 = fmaxf(tm0, __shfl_xor_sync(0xffffffffu, tm0, 2));
        tm1 = fmaxf(tm1, __shfl_xor_sync(0xffffffffu, tm1, 1));
        tm1 = fmaxf(tm1, __shfl_xor_sync(0xffffffffu, tm1, 2));

        const float mn0 = fmaxf(m0, tm0), mn1 = fmaxf(m1, tm1);
        const float c0 = ex2f(m0 - mn0), c1 = ex2f(m1 - mn1);
        m0 = mn0; m1 = mn1;

        #pragma unroll
        for (int nt = 0; nt < 8; nt++) {
            o[nt][0] *= c0; o[nt][1] *= c0;
            o[nt][2] *= c1; o[nt][3] *= c1;
        }

        // ---- P = ex2(S-m) f16; row sums via MMA; O += P V ----
        float dsum[4] = {0.f, 0.f, 0.f, 0.f};
        #pragma unroll
        for (int kc = 0; kc < 4; kc++) {
            const float* p0 = cur[2 * kc];
            const float* p1 = cur[2 * kc + 1];
            uint32_t ph[4];
            ph[0] = ex2h2(packh2(p0[0] - mn0, p0[1] - mn0));
            ph[1] = ex2h2(packh2(p0[2] - mn1, p0[3] - mn1));
            ph[2] = ex2h2(packh2(p1[0] - mn0, p1[1] - mn0));
            ph[3] = ex2h2(packh2(p1[2] - mn1, p1[3] - mn1));

            mma_f16(dsum, ph, ONES2);

            const int rowV = rVbase + kc * 16;
            #pragma unroll
            for (int nt16 = 0; nt16 < 4; nt16++) {
                uint32_t vf[4];
                ldm_x4_t(vf, stV + aswz(rowV, chV + nt16 * 2));
                #pragma unroll
                for (int hf = 0; hf < 2; hf++)
                    mma_f16(o[nt16 * 2 + hf], ph, &vf[hf * 2]);
            }
        }
        l0 = l0 * c0 + dsum[0];
        l1 = l1 * c1 + dsum[2];
    };

    #pragma unroll 1
    for (int kt = 0; kt < KT; kt += 2) {   // KT is even
        step(kt,     sA, sB);
        step(kt + 1, sB, sA);
    }

    // ---- finalize ----
    const float inv0 = 1.f / l0, inv1 = 1.f / l1;

    const size_t row0 = (size_t)b * T_ + qb * 128 + wid * 16 + (lane >> 2);
    const size_t row1 = row0 + 8;
    const int colB = h * HD_ + (lane & 3) * 2;

    #pragma unroll
    for (int nt = 0; nt < 8; nt++) {
        const size_t i0 = row0 * D_ + colB + nt * 8;
        const size_t i1 = row1 * D_ + colB + nt * 8;
        reinterpret_cast<uint32_t*>(g_o16)[i0 >> 1] =
            packh2(o[nt][0] * inv0, o[nt][1] * inv0);
        reinterpret_cast<uint32_t*>(g_o16)[i1 >> 1] =
            packh2(o[nt][2] * inv1, o[nt][3] * inv1);
    }
}

// ---------------------------------------------------------------------------
// Conversion kernels
// ---------------------------------------------------------------------------
__global__ __launch_bounds__(256) void quant_x_kernel(const float* __restrict__ src)
{
    const int i = blockIdx.x * 256 + threadIdx.x;
    g_x16[i] = __float2half_rn(src[i]);
}

// transpose + quantize 4 weights; also resets persistent-GEMM counters
__global__ __launch_bounds__(256) void wquant_kernel(
    const float* __restrict__ wq, const float* __restrict__ wk,
    const float* __restrict__ wv, const float* __restrict__ wo)
{
    if (blockIdx.x == 0 && blockIdx.y == 0 && blockIdx.z == 0 &&
        threadIdx.x == 0) {
        g_ctr[0] = 0;
        g_ctr[1] = 0;
    }

    __shared__ float tile[32][33];
    const int z = blockIdx.z;
    const float* w = (z == 0) ? wq : (z == 1) ? wk : (z == 2) ? wv : wo;
    const int nB = blockIdx.x * 32, kB = blockIdx.y * 32;
    const int tx = threadIdx.x & 31, ty = threadIdx.x >> 5;

    #pragma unroll
    for (int r = ty; r < 32; r += 8)
        tile[r][tx] = w[(size_t)(kB + r) * D_ + nB + tx];
    __syncthreads();
    #pragma unroll
    for (int r = ty; r < 32; r += 8) {
        const size_t di = ((size_t)z << 20) + (size_t)(nB + r) * D_ + kB + tx;
        g_wt[di] = __float2half_rn(tile[tx][r]);
    }
}

// ---------------------------------------------------------------------------
extern "C" void kernel_launch(void* const* d_in, const int* in_sizes, int n_in,
                              void* d_out, int out_size)
{
    const float* x  = (const float*)d_in[0];
    const float* wq = (const float*)d_in[1];
    const float* bq = (const float*)d_in[2];
    const float* wk = (const float*)d_in[3];
    const float* bk = (const float*)d_in[4];
    const float* wv = (const float*)d_in[5];
    const float* bv = (const float*)d_in[6];
    const float* wo = (const float*)d_in[7];
    const float* bo = (const float*)d_in[8];
    float* out = (float*)d_out;

    static bool attrSet = false;
    if (!attrSet) {
        cudaFuncSetAttribute(gemm_mma<0>,
                             cudaFuncAttributeMaxDynamicSharedMemorySize, GEMM_SMEM);
        cudaFuncSetAttribute(gemm_mma<1>,
                             cudaFuncAttributeMaxDynamicSharedMemorySize, GEMM_SMEM);
        cudaFuncSetAttribute(attn_mma,
                             cudaFuncAttributeMaxDynamicSharedMemorySize, ATT_SMEM);
        attrSet = true;
    }

    void *px16, *po16;
    cudaGetSymbolAddress(&px16, g_x16);
    cudaGetSymbolAddress(&po16, g_o16);

    const int nElem = M_ * D_;

    // 1) convert inputs (wquant also resets the persistent tile counters)
    quant_x_kernel<<<nElem / 256, 256>>>(x);
    wquant_kernel<<<dim3(32, 32, 4), 256>>>(wq, wk, wv, wo);

    // 2) QKV projections (persistent, 1536 tiles) -> q/k/v f16 [B,H,T,HD]
    gemm_mma<0><<<GEMM_GRID, 256, GEMM_SMEM>>>(
        (const __half*)px16, bq, bk, bv, nullptr);

    // 3) tensor-core causal flash attention -> g_o16 [B*T, D]
    attn_mma<<<dim3(T_ / 128, H_, B_), 256, ATT_SMEM>>>();

    // 4) output projection (persistent, 512 tiles)
    gemm_mma<1><<<GEMM_GRID, 256, GEMM_SMEM>>>(
        (const __half*)po16, bo, nullptr, nullptr, out);
}

// round 13
// speedup vs baseline: 1.0458x; 1.0458x over previous
#include <cuda_runtime.h>
#include <cuda_fp16.h>
#include <cstdint>
#include <cstddef>

// ---------------------------------------------------------------------------
// Problem constants
// ---------------------------------------------------------------------------
constexpr int B_  = 4;
constexpr int T_  = 2048;
constexpr int D_  = 1024;
constexpr int H_  = 16;
constexpr int HD_ = 64;
constexpr int M_  = B_ * T_;   // 8192

// 0.125 * log2(e): folded into Q so softmax uses exp2
constexpr float QSCALE = 0.18033688011112042f;

// ---------------------------------------------------------------------------
// Device scratch (pure f16 pipeline, fp32 accumulation in-kernel)
// ---------------------------------------------------------------------------
__device__ __align__(128) __half g_x16[(size_t)M_ * D_];   // x f16
__device__ __align__(128) __half g_o16[(size_t)M_ * D_];   // attnO f16 [B*T, D]
__device__ __align__(128) __half g_q16[(size_t)M_ * D_];   // [B,H,T,HD]
__device__ __align__(128) __half g_k16[(size_t)M_ * D_];
__device__ __align__(128) __half g_v16[(size_t)M_ * D_];
// 4 weights transposed to [N, K] f16, z: 0..3 -> wq,wk,wv,wo
__device__ __align__(128) __half g_wt[(size_t)4 * D_ * D_];
// persistent-GEMM tile counters (reset by wquant each call)
__device__ unsigned int g_ctr[2];

// ---------------------------------------------------------------------------
// PTX helpers
// ---------------------------------------------------------------------------
__device__ __forceinline__ uint32_t smem_u32(const void* p) {
    uint32_t a;
    asm("{ .reg .u64 t; cvta.to.shared.u64 t, %1; cvt.u32.u64 %0, t; }"
        : "=r"(a) : "l"(p));
    return a;
}
__device__ __forceinline__ void cp16(uint32_t saddr, const void* gaddr) {
    asm volatile("cp.async.cg.shared.global [%0], [%1], 16;"
                 :: "r"(saddr), "l"(gaddr));
}
__device__ __forceinline__ void cp_commit() {
    asm volatile("cp.async.commit_group;");
}
template <int N>
__device__ __forceinline__ void cp_wait() {
    asm volatile("cp.async.wait_group %0;" :: "n"(N));
}
__device__ __forceinline__ void ldm_x4(uint32_t* r, uint32_t addr) {
    asm volatile("ldmatrix.sync.aligned.m8n8.x4.shared.b16 {%0,%1,%2,%3}, [%4];"
                 : "=r"(r[0]), "=r"(r[1]), "=r"(r[2]), "=r"(r[3]) : "r"(addr));
}
__device__ __forceinline__ void ldm_x4_t(uint32_t* r, uint32_t addr) {
    asm volatile("ldmatrix.sync.aligned.m8n8.x4.trans.shared.b16 {%0,%1,%2,%3}, [%4];"
                 : "=r"(r[0]), "=r"(r[1]), "=r"(r[2]), "=r"(r[3]) : "r"(addr));
}
__device__ __forceinline__ void mma_f16(float* c, const uint32_t* a,
                                        const uint32_t* b) {
    asm volatile(
        "mma.sync.aligned.m16n8k16.row.col.f32.f16.f16.f32 "
        "{%0,%1,%2,%3}, {%4,%5,%6,%7}, {%8,%9}, {%0,%1,%2,%3};"
        : "+f"(c[0]), "+f"(c[1]), "+f"(c[2]), "+f"(c[3])
        : "r"(a[0]), "r"(a[1]), "r"(a[2]), "r"(a[3]), "r"(b[0]), "r"(b[1]));
}
__device__ __forceinline__ float ex2f(float x) {
    float r;
    asm("ex2.approx.ftz.f32 %0, %1;" : "=f"(r) : "f"(x));
    return r;
}
// packed f16x2: {low=lo, high=hi}
__device__ __forceinline__ uint32_t packh2(float lo, float hi) {
    uint32_t r;
    asm("cvt.rn.f16x2.f32 %0, %1, %2;" : "=r"(r) : "f"(hi), "f"(lo));
    return r;
}
__device__ __forceinline__ uint32_t ex2h2(uint32_t x) {
    uint32_t r;
    asm("ex2.approx.f16x2 %0, %1;" : "=r"(r) : "r"(x));
    return r;
}

// ---------------------------------------------------------------------------
// Persistent HMMA GEMM, 1-term f16: C = A16 @ W16^T + bias, fp32 accum.
// grid = 296 CTAs (2/SM), atomic tile counter; per tile: 8 warps (4Mx2N),
// warp 32x64, BK=32, 6-stage cp.async ring, single sync per kt.
// MODE 0: tiles z in {0,1,2} -> q/k/v f16 [B,H,T,HD]; Q pre-scaled.
// MODE 1: z = 3 -> out fp32 [M, D].
// ---------------------------------------------------------------------------
constexpr int BK        = 32;
constexpr int G_ARR_B   = 128 * 64;                   // 8192 B per tile array
constexpr int G_STAGE_B = 2 * G_ARR_B;                // 16384 (A, W)
constexpr int G_NSTG    = 6;
constexpr int GEMM_SMEM = G_NSTG * G_STAGE_B + 128;   // ring + control slot
constexpr int KT_G      = D_ / BK;                    // 32
constexpr int GEMM_GRID = 296;

__device__ __forceinline__ uint32_t gswz(int row, int chunk) {
    return (uint32_t)row * 64u + (uint32_t)((chunk ^ ((row >> 1) & 3)) << 4);
}

template <int MODE>
__global__ __launch_bounds__(256, 2)
void gemm_mma(const __half* __restrict__ A,
              const float* __restrict__ b0, const float* __restrict__ b1,
              const float* __restrict__ b2,
              float* __restrict__ out)
{
    extern __shared__ __align__(128) char smem[];
    const uint32_t sb = smem_u32(smem);
    int* tileSlot = reinterpret_cast<int*>(smem + G_NSTG * G_STAGE_B);

    constexpr int NT = (MODE == 0) ? 1536 : 512;

    const int tid  = threadIdx.x;
    const int wid  = tid >> 5;
    const int lane = tid & 31;
    const int wm   = (wid & 3) * 32;
    const int wn   = (wid >> 2) * 64;

    const int c0r = tid >> 2,         c0q = tid & 3;
    const int c1r = (tid + 256) >> 2, c1q = (tid + 256) & 3;
    const uint32_t s0 = gswz(c0r, c0q), s1 = gswz(c1r, c1q);

    int rowA[2], rowB[4];
    #pragma unroll
    for (int mi = 0; mi < 2; mi++)
        rowA[mi] = wm + (lane & 7) + ((lane >> 3) & 1) * 8 + mi * 16;
    #pragma unroll
    for (int p = 0; p < 4; p++)
        rowB[p] = wn + ((lane >> 4) & 1) * 8 + (lane & 7) + p * 16;
    const int chA = (lane >> 4) & 1;
    const int chB = (lane >> 3) & 1;

    for (;;) {
        __syncthreads();                   // ring + control safe to reuse
        if (tid == 0)
            *tileSlot = (int)atomicAdd(&g_ctr[MODE], 1u);
        __syncthreads();
        const int tile = *tileSlot;
        if (tile >= NT) break;

        const int z     = (MODE == 0) ? (tile >> 9) : 3;
        const int rem   = tile & 511;
        const int mBase = (rem >> 3) * 128;
        const int nBase = (rem & 7) * 128;
        const __half* W = g_wt + ((size_t)z << 20);

        auto load_stage = [&](int stg, int kt) {
            const uint32_t st = sb + stg * G_STAGE_B;
            const int bk = kt * BK;
            cp16(st + s0, A + (size_t)(mBase + c0r) * D_ + bk + c0q * 8);
            cp16(st + s1, A + (size_t)(mBase + c1r) * D_ + bk + c1q * 8);
            cp16(st + G_ARR_B + s0, W + (size_t)(nBase + c0r) * D_ + bk + c0q * 8);
            cp16(st + G_ARR_B + s1, W + (size_t)(nBase + c1r) * D_ + bk + c1q * 8);
            cp_commit();
        };

        float acc[2][8][4];
        #pragma unroll
        for (int mi = 0; mi < 2; mi++)
            #pragma unroll
            for (int ni = 0; ni < 8; ni++)
                #pragma unroll
                for (int r = 0; r < 4; r++) acc[mi][ni][r] = 0.f;

        #pragma unroll
        for (int j = 0; j < 5; j++) load_stage(j, j);

        #pragma unroll 1
        for (int kt = 0; kt < KT_G; kt++) {
            cp_wait<4>();
            __syncthreads();

            if (kt + 5 < KT_G) load_stage((kt + 5) % G_NSTG, kt + 5);
            else               cp_commit();

            const uint32_t st = sb + (kt % G_NSTG) * G_STAGE_B;
            const uint32_t sA = st;
            const uint32_t sW = st + G_ARR_B;

            #pragma unroll
            for (int ks = 0; ks < 2; ks++) {
                uint32_t af[2][4];
                #pragma unroll
                for (int mi = 0; mi < 2; mi++)
                    ldm_x4(af[mi], sA + gswz(rowA[mi], chA + ks * 2));
                uint32_t bf[4][4];
                #pragma unroll
                for (int p = 0; p < 4; p++)
                    ldm_x4(bf[p], sW + gswz(rowB[p], chB + ks * 2));
                #pragma unroll
                for (int mi = 0; mi < 2; mi++)
                    #pragma unroll
                    for (int p = 0; p < 4; p++)
                        #pragma unroll
                        for (int hf = 0; hf < 2; hf++)
                            mma_f16(acc[mi][p * 2 + hf], af[mi], &bf[p][hf * 2]);
            }
        }
        cp_wait<0>();   // drain tail empty groups before ring reuse next tile

        // --- epilogue ---
        const float* bias;
        __half* dst16 = nullptr;
        float scale = 1.f;
        if (MODE == 0) {
            if (z == 0)      { dst16 = g_q16; bias = b0; scale = QSCALE; }
            else if (z == 1) { dst16 = g_k16; bias = b1; }
            else             { dst16 = g_v16; bias = b2; }
        } else {
            bias = b0;
        }

        #pragma unroll
        for (int mi = 0; mi < 2; mi++) {
            #pragma unroll
            for (int ni = 0; ni < 8; ni++) {
                const int n0 = nBase + wn + ni * 8 + (lane & 3) * 2;
                const float bv0 = __ldg(bias + n0), bv1 = __ldg(bias + n0 + 1);
                #pragma unroll
                for (int rr = 0; rr < 2; rr++) {
                    const int m = mBase + wm + mi * 16 + (lane >> 2) + rr * 8;
                    float v0 = acc[mi][ni][rr * 2 + 0] + bv0;
                    float v1 = acc[mi][ni][rr * 2 + 1] + bv1;
                    if (MODE == 0) {
                        v0 *= scale; v1 *= scale;
                        const int bb = m >> 11, tt = m & 2047;
                        const int hh = n0 >> 6, hd = n0 & 63;
                        const size_t idx =
                            ((((size_t)bb * H_ + hh) * T_ + tt) << 6) + hd;
                        reinterpret_cast<uint32_t*>(dst16)[idx >> 1] =
                            packh2(v0, v1);
                    } else {
                        *reinterpret_cast<float2*>(out + (size_t)m * D_ + n0) =
                            make_float2(v0, v1);
                    }
                }
            }
        }
    }
}

// ---------------------------------------------------------------------------
// Tensor-core causal flash attention, pure f16 operands, fp32 accum.
// (R11 design: Q fragments register-resident, serial per-tile softmax,
//  6-stage KV ring, single sync per iteration, 2 CTAs/SM.)
// ---------------------------------------------------------------------------
constexpr int ATT_ARR_B   = 64 * 128;                 // 8192 per array
constexpr int ATT_STAGE_B = 2 * ATT_ARR_B;            // 16384 (k, v)
constexpr int ATT_NSTG    = 6;
constexpr int ATT_SMEM    = ATT_NSTG * ATT_STAGE_B;   // 98304 -> 2 CTAs/SM

__device__ __forceinline__ uint32_t aswz(int row, int chunk) {
    return (uint32_t)row * 128u + (uint32_t)((chunk ^ (row & 7)) << 4);
}

__global__ __launch_bounds__(256, 2)
void attn_mma()
{
    extern __shared__ __align__(128) char smem[];
    const uint32_t sb = smem_u32(smem);

    const int tid  = threadIdx.x;
    const int wid  = tid >> 5;
    const int lane = tid & 31;

    const int qb = (gridDim.x - 1) - blockIdx.x;     // largest-first
    const int h  = blockIdx.y, b = blockIdx.z;
    const size_t bh = ((size_t)(b * H_ + h)) * T_ * HD_;

    const __half* Q = g_q16 + bh + (size_t)qb * 128 * HD_;
    const __half* K = g_k16 + bh;
    const __half* V = g_v16 + bh;

    const int KT = 2 * qb + 2;   // >= 2

    // ---- Q via ring stage 0 (128 rows x 128B = 16KB), then to registers ----
    #pragma unroll
    for (int i = 0; i < 4; i++) {
        const int c = i * 256 + tid;
        const int row = c >> 3, q8 = c & 7;
        cp16(sb + aswz(row, q8), Q + (size_t)row * HD_ + q8 * 8);
    }
    cp_commit();
    cp_wait<0>();
    __syncthreads();

    uint32_t qf[4][4];
    {
        const int rowQ = wid * 16 + (lane & 7) + ((lane >> 3) & 1) * 8;
        const int chQ  = (lane >> 4) & 1;
        #pragma unroll
        for (int kc = 0; kc < 4; kc++)
            ldm_x4(qf[kc], sb + aswz(rowQ, chQ + kc * 2));
    }
    __syncthreads();             // all warps done reading Q smem

    auto load_kv = [&](int stg, int kt) {
        const uint32_t base = sb + stg * ATT_STAGE_B;
        #pragma unroll
        for (int i = 0; i < 4; i++) {                // 2 arrays * 512 chunks
            const int c = i * 256 + tid;
            const int arr = c >> 9, row = (c >> 3) & 63, q8 = c & 7;
            const __half* g = arr ? V : K;
            cp16(base + arr * ATT_ARR_B + aswz(row, q8),
                 g + (size_t)(kt * 64 + row) * HD_ + q8 * 8);
        }
        cp_commit();
    };
    // prologue: fill stages 0..4 (empty commits past KT)
    #pragma unroll
    for (int j = 0; j < 5; j++) {
        if (j < KT) load_kv(j, j);
        else        cp_commit();
    }

    float o[8][4];
    #pragma unroll
    for (int nt = 0; nt < 8; nt++)
        #pragma unroll
        for (int r = 0; r < 4; r++) o[nt][r] = 0.f;
    float m0 = -1e30f, m1 = -1e30f, l0 = 0.f, l1 = 0.f;

    const int r0g = qb * 128 + wid * 16 + (lane >> 2);

    const int rKbase = ((lane >> 4) & 1) * 8 + (lane & 7);
    const int chK    = (lane >> 3) & 1;
    const int rVbase = (lane & 7) + ((lane >> 3) & 1) * 8;
    const int chV    = (lane >> 4) & 1;

    const uint32_t ONES2[2] = {0x3C003C00u, 0x3C003C00u};

    #pragma unroll 1
    for (int kt = 0; kt < KT; kt++) {
        cp_wait<4>();            // stage kt ready
        __syncthreads();         // all warps done with stage kt-1

        if (kt + 5 < KT) load_kv((kt + 5) % ATT_NSTG, kt + 5);
        else             cp_commit();

        const uint32_t st  = sb + (kt % ATT_NSTG) * ATT_STAGE_B;
        const uint32_t stK = st;
        const uint32_t stV = st + ATT_ARR_B;

        // ---- S = q16 . k16 ----
        float s[8][4];
        #pragma unroll
        for (int nt = 0; nt < 8; nt++)
            #pragma unroll
            for (int r = 0; r < 4; r++) s[nt][r] = 0.f;

        #pragma unroll
        for (int kc = 0; kc < 4; kc++) {
            #pragma unroll
            for (int g = 0; g < 2; g++) {
                uint32_t kf[2][4];
                #pragma unroll
                for (int t = 0; t < 2; t++) {
                    const int nt16 = g * 2 + t;
                    ldm_x4(kf[t], stK + aswz(rKbase + nt16 * 16, chK + kc * 2));
                }
                #pragma unroll
                for (int t = 0; t < 2; t++)
                    #pragma unroll
                    for (int hf = 0; hf < 2; hf++)
                        mma_f16(s[(g * 2 + t) * 2 + hf], qf[kc], &kf[t][hf * 2]);
            }
        }

        // ---- causal mask (last two tiles only) ----
        if (kt >= KT - 2) {
            const int colBase = kt * 64 + (lane & 3) * 2;
            #pragma unroll
            for (int nt = 0; nt < 8; nt++)
                #pragma unroll
                for (int j = 0; j < 2; j++) {
                    const int c = colBase + nt * 8 + j;
                    if (c > r0g)     s[nt][j]     = -30000.f;
                    if (c > r0g + 8) s[nt][2 + j] = -30000.f;
                }
        }

        // ---- max-reduce + o rescale ----
        float tm0 = -1e30f, tm1 = -1e30f;
        #pragma unroll
        for (int nt = 0; nt < 8; nt++) {
            tm0 = fmaxf(tm0, fmaxf(s[nt][0], s[nt][1]));
            tm1 = fmaxf(tm1, fmaxf(s[nt][2], s[nt][3]));
        }
        tm0 = fmaxf(tm0, __shfl_xor_sync(0xffffffffu, tm0, 1));
        tm0 = fmaxf(tm0, __shfl_xor_sync(0xffffffffu, tm0, 2));
        tm1 = fmaxf(tm1, __shfl_xor_sync(0xffffffffu, tm1, 1));
        tm1 = fmaxf(tm1, __shfl_xor_sync(0xffffffffu, tm1, 2));

        const float mn0 = fmaxf(m0, tm0), mn1 = fmaxf(m1, tm1);
        const float c0 = ex2f(m0 - mn0), c1 = ex2f(m1 - mn1);
        m0 = mn0; m1 = mn1;

        #pragma unroll
        for (int nt = 0; nt < 8; nt++) {
            o[nt][0] *= c0; o[nt][1] *= c0;
            o[nt][2] *= c1; o[nt][3] *= c1;
        }

        // ---- P = ex2(S-m) f16; row sums via MMA; O += P V ----
        float dsum[4] = {0.f, 0.f, 0.f, 0.f};
        #pragma unroll
        for (int kc = 0; kc < 4; kc++) {
            const float* s0 = s[2 * kc];
            const float* s1 = s[2 * kc + 1];
            uint32_t ph[4];
            ph[0] = ex2h2(packh2(s0[0] - mn0, s0[1] - mn0));
            ph[1] = ex2h2(packh2(s0[2] - mn1, s0[3] - mn1));
            ph[2] = ex2h2(packh2(s1[0] - mn0, s1[1] - mn0));
            ph[3] = ex2h2(packh2(s1[2] - mn1, s1[3] - mn1));

            mma_f16(dsum, ph, ONES2);

            const int rowV = rVbase + kc * 16;
            #pragma unroll
            for (int nt16 = 0; nt16 < 4; nt16++) {
                uint32_t vf[4];
                ldm_x4_t(vf, stV + aswz(rowV, chV + nt16 * 2));
                #pragma unroll
                for (int hf = 0; hf < 2; hf++)
                    mma_f16(o[nt16 * 2 + hf], ph, &vf[hf * 2]);
            }
        }
        l0 = l0 * c0 + dsum[0];
        l1 = l1 * c1 + dsum[2];
    }

    // ---- finalize: single f16 plane out ----
    const float inv0 = 1.f / l0, inv1 = 1.f / l1;

    const size_t row0 = (size_t)b * T_ + qb * 128 + wid * 16 + (lane >> 2);
    const size_t row1 = row0 + 8;
    const int colB = h * HD_ + (lane & 3) * 2;

    #pragma unroll
    for (int nt = 0; nt < 8; nt++) {
        const size_t i0 = row0 * D_ + colB + nt * 8;
        const size_t i1 = row1 * D_ + colB + nt * 8;
        reinterpret_cast<uint32_t*>(g_o16)[i0 >> 1] =
            packh2(o[nt][0] * inv0, o[nt][1] * inv0);
        reinterpret_cast<uint32_t*>(g_o16)[i1 >> 1] =
            packh2(o[nt][2] * inv1, o[nt][3] * inv1);
    }
}

// ---------------------------------------------------------------------------
// Conversion kernels
// ---------------------------------------------------------------------------
__global__ __launch_bounds__(256) void quant_x_kernel(const float* __restrict__ src)
{
    const int i = blockIdx.x * 256 + threadIdx.x;
    g_x16[i] = __float2half_rn(src[i]);
}

// transpose + quantize 4 weights; also resets persistent-GEMM counters
__global__ __launch_bounds__(256) void wquant_kernel(
    const float* __restrict__ wq, const float* __restrict__ wk,
    const float* __restrict__ wv, const float* __restrict__ wo)
{
    if (blockIdx.x == 0 && blockIdx.y == 0 && blockIdx.z == 0 &&
        threadIdx.x == 0) {
        g_ctr[0] = 0;
        g_ctr[1] = 0;
    }

    __shared__ float tile[32][33];
    const int z = blockIdx.z;
    const float* w = (z == 0) ? wq : (z == 1) ? wk : (z == 2) ? wv : wo;
    const int nB = blockIdx.x * 32, kB = blockIdx.y * 32;
    const int tx = threadIdx.x & 31, ty = threadIdx.x >> 5;

    #pragma unroll
    for (int r = ty; r < 32; r += 8)
        tile[r][tx] = w[(size_t)(kB + r) * D_ + nB + tx];
    __syncthreads();
    #pragma unroll
    for (int r = ty; r < 32; r += 8) {
        const size_t di = ((size_t)z << 20) + (size_t)(nB + r) * D_ + kB + tx;
        g_wt[di] = __float2half_rn(tile[tx][r]);
    }
}

// ---------------------------------------------------------------------------
extern "C" void kernel_launch(void* const* d_in, const int* in_sizes, int n_in,
                              void* d_out, int out_size)
{
    const float* x  = (const float*)d_in[0];
    const float* wq = (const float*)d_in[1];
    const float* bq = (const float*)d_in[2];
    const float* wk = (const float*)d_in[3];
    const float* bk = (const float*)d_in[4];
    const float* wv = (const float*)d_in[5];
    const float* bv = (const float*)d_in[6];
    const float* wo = (const float*)d_in[7];
    const float* bo = (const float*)d_in[8];
    float* out = (float*)d_out;

    static bool attrSet = false;
    if (!attrSet) {
        cudaFuncSetAttribute(gemm_mma<0>,
                             cudaFuncAttributeMaxDynamicSharedMemorySize, GEMM_SMEM);
        cudaFuncSetAttribute(gemm_mma<1>,
                             cudaFuncAttributeMaxDynamicSharedMemorySize, GEMM_SMEM);
        cudaFuncSetAttribute(attn_mma,
                             cudaFuncAttributeMaxDynamicSharedMemorySize, ATT_SMEM);
        attrSet = true;
    }

    void *px16, *po16;
    cudaGetSymbolAddress(&px16, g_x16);
    cudaGetSymbolAddress(&po16, g_o16);

    const int nElem = M_ * D_;

    // 1) convert inputs (wquant also resets the persistent tile counters)
    quant_x_kernel<<<nElem / 256, 256>>>(x);
    wquant_kernel<<<dim3(32, 32, 4), 256>>>(wq, wk, wv, wo);

    // 2) QKV projections (persistent, 1536 tiles) -> q/k/v f16 [B,H,T,HD]
    gemm_mma<0><<<GEMM_GRID, 256, GEMM_SMEM>>>(
        (const __half*)px16, bq, bk, bv, nullptr);

    // 3) tensor-core causal flash attention -> g_o16 [B*T, D]
    attn_mma<<<dim3(T_ / 128, H_, B_), 256, ATT_SMEM>>>();

    // 4) output projection (persistent, 512 tiles)
    gemm_mma<1><<<GEMM_GRID, 256, GEMM_SMEM>>>(
        (const __half*)po16, bo, nullptr, nullptr, out);
}

// round 14
// speedup vs baseline: 1.1675x; 1.1163x over previous
#include <cuda_runtime.h>
#include <cuda_fp16.h>
#include <cstdint>
#include <cstddef>

// ---------------------------------------------------------------------------
// Problem constants
// ---------------------------------------------------------------------------
constexpr int B_  = 4;
constexpr int T_  = 2048;
constexpr int D_  = 1024;
constexpr int H_  = 16;
constexpr int HD_ = 64;
constexpr int M_  = B_ * T_;   // 8192

// 0.125 * log2(e): folded into Q so softmax uses exp2
constexpr float QSCALE = 0.18033688011112042f;

// ---------------------------------------------------------------------------
// Device scratch (pure f16 pipeline, fp32 accumulation in-kernel)
// ---------------------------------------------------------------------------
__device__ __align__(128) __half g_x16[(size_t)M_ * D_];   // x f16
__device__ __align__(128) __half g_o16[(size_t)M_ * D_];   // attnO f16 [B*T, D]
__device__ __align__(128) __half g_q16[(size_t)M_ * D_];   // [B,H,T,HD]
__device__ __align__(128) __half g_k16[(size_t)M_ * D_];
__device__ __align__(128) __half g_v16[(size_t)M_ * D_];
// 4 weights transposed to [N, K] f16, z: 0..3 -> wq,wk,wv,wo
__device__ __align__(128) __half g_wt[(size_t)4 * D_ * D_];
// persistent-GEMM tile counters (reset by wquant each call)
__device__ unsigned int g_ctr[2];

// ---------------------------------------------------------------------------
// PTX helpers
// ---------------------------------------------------------------------------
__device__ __forceinline__ uint32_t smem_u32(const void* p) {
    uint32_t a;
    asm("{ .reg .u64 t; cvta.to.shared.u64 t, %1; cvt.u32.u64 %0, t; }"
        : "=r"(a) : "l"(p));
    return a;
}
__device__ __forceinline__ void cp16(uint32_t saddr, const void* gaddr) {
    asm volatile("cp.async.cg.shared.global [%0], [%1], 16;"
                 :: "r"(saddr), "l"(gaddr));
}
__device__ __forceinline__ void cp_commit() {
    asm volatile("cp.async.commit_group;");
}
template <int N>
__device__ __forceinline__ void cp_wait() {
    asm volatile("cp.async.wait_group %0;" :: "n"(N));
}
__device__ __forceinline__ void ldm_x4(uint32_t* r, uint32_t addr) {
    asm volatile("ldmatrix.sync.aligned.m8n8.x4.shared.b16 {%0,%1,%2,%3}, [%4];"
                 : "=r"(r[0]), "=r"(r[1]), "=r"(r[2]), "=r"(r[3]) : "r"(addr));
}
__device__ __forceinline__ void ldm_x4_t(uint32_t* r, uint32_t addr) {
    asm volatile("ldmatrix.sync.aligned.m8n8.x4.trans.shared.b16 {%0,%1,%2,%3}, [%4];"
                 : "=r"(r[0]), "=r"(r[1]), "=r"(r[2]), "=r"(r[3]) : "r"(addr));
}
__device__ __forceinline__ void mma_f16(float* c, const uint32_t* a,
                                        const uint32_t* b) {
    asm volatile(
        "mma.sync.aligned.m16n8k16.row.col.f32.f16.f16.f32 "
        "{%0,%1,%2,%3}, {%4,%5,%6,%7}, {%8,%9}, {%0,%1,%2,%3};"
        : "+f"(c[0]), "+f"(c[1]), "+f"(c[2]), "+f"(c[3])
        : "r"(a[0]), "r"(a[1]), "r"(a[2]), "r"(a[3]), "r"(b[0]), "r"(b[1]));
}
__device__ __forceinline__ float ex2f(float x) {
    float r;
    asm("ex2.approx.ftz.f32 %0, %1;" : "=f"(r) : "f"(x));
    return r;
}
// packed f16x2: {low=lo, high=hi}
__device__ __forceinline__ uint32_t packh2(float lo, float hi) {
    uint32_t r;
    asm("cvt.rn.f16x2.f32 %0, %1, %2;" : "=r"(r) : "f"(hi), "f"(lo));
    return r;
}
__device__ __forceinline__ uint32_t ex2h2(uint32_t x) {
    uint32_t r;
    asm("ex2.approx.f16x2 %0, %1;" : "=r"(r) : "r"(x));
    return r;
}

// 128B-pitch SW128 swizzle: byte offset of (row, 16B-chunk)
__device__ __forceinline__ uint32_t swz128(int row, int chunk) {
    return (uint32_t)row * 128u + (uint32_t)((chunk ^ (row & 7)) << 4);
}

// ---------------------------------------------------------------------------
// Persistent HMMA GEMM, 1-term f16: C = A16 @ W16^T + bias, fp32 accum.
// grid = 296 CTAs (2/SM), atomic tile counter; per tile: 8 warps (4Mx2N),
// warp 32x64, BK=64 (full SW128 rows), 3-stage 32KB ring, single sync/kt.
// MODE 0: tiles z in {0,1,2} -> q/k/v f16 [B,H,T,HD]; Q pre-scaled.
// MODE 1: z = 3 -> out fp32 [M, D].
// ---------------------------------------------------------------------------
constexpr int BK        = 64;
constexpr int G_ARR_B   = 128 * 128;                  // 16384 B per tile array
constexpr int G_STAGE_B = 2 * G_ARR_B;                // 32768 (A, W)
constexpr int G_NSTG    = 3;
constexpr int GEMM_SMEM = G_NSTG * G_STAGE_B + 128;   // ring + control slot
constexpr int KT_G      = D_ / BK;                    // 16
constexpr int GEMM_GRID = 296;

template <int MODE>
__global__ __launch_bounds__(256, 2)
void gemm_mma(const __half* __restrict__ A,
              const float* __restrict__ b0, const float* __restrict__ b1,
              const float* __restrict__ b2,
              float* __restrict__ out)
{
    extern __shared__ __align__(128) char smem[];
    const uint32_t sb = smem_u32(smem);
    int* tileSlot = reinterpret_cast<int*>(smem + G_NSTG * G_STAGE_B);

    constexpr int NT = (MODE == 0) ? 1536 : 512;

    const int tid  = threadIdx.x;
    const int wid  = tid >> 5;
    const int lane = tid & 31;
    const int wm   = (wid & 3) * 32;
    const int wn   = (wid >> 2) * 64;

    int rowA[2], rowB[4];
    #pragma unroll
    for (int mi = 0; mi < 2; mi++)
        rowA[mi] = wm + (lane & 7) + ((lane >> 3) & 1) * 8 + mi * 16;
    #pragma unroll
    for (int p = 0; p < 4; p++)
        rowB[p] = wn + ((lane >> 4) & 1) * 8 + (lane & 7) + p * 16;
    const int chA = (lane >> 4) & 1;
    const int chB = (lane >> 3) & 1;

    for (;;) {
        __syncthreads();                   // ring + control safe to reuse
        if (tid == 0)
            *tileSlot = (int)atomicAdd(&g_ctr[MODE], 1u);
        __syncthreads();
        const int tile = *tileSlot;
        if (tile >= NT) break;

        const int z     = (MODE == 0) ? (tile >> 9) : 3;
        const int rem   = tile & 511;
        const int mBase = (rem >> 3) * 128;
        const int nBase = (rem & 7) * 128;
        const __half* W = g_wt + ((size_t)z << 20);

        auto load_stage = [&](int stg, int kt) {
            const uint32_t st = sb + stg * G_STAGE_B;
            const int bk = kt * BK;
            #pragma unroll
            for (int j = 0; j < 4; j++) {       // 1024 chunks per array
                const int c = j * 256 + tid;
                const int row = c >> 3, q8 = c & 7;
                const uint32_t off = swz128(row, q8);
                cp16(st + off,
                     A + (size_t)(mBase + row) * D_ + bk + q8 * 8);
                cp16(st + G_ARR_B + off,
                     W + (size_t)(nBase + row) * D_ + bk + q8 * 8);
            }
            cp_commit();
        };

        float acc[2][8][4];
        #pragma unroll
        for (int mi = 0; mi < 2; mi++)
            #pragma unroll
            for (int ni = 0; ni < 8; ni++)
                #pragma unroll
                for (int r = 0; r < 4; r++) acc[mi][ni][r] = 0.f;

        load_stage(0, 0);
        load_stage(1, 1);

        #pragma unroll 1
        for (int kt = 0; kt < KT_G; kt++) {
            cp_wait<1>();            // stage kt ready
            __syncthreads();         // all warps done with stage kt-1

            if (kt + 2 < KT_G) load_stage((kt + 2) % G_NSTG, kt + 2);
            else               cp_commit();

            const uint32_t st = sb + (kt % G_NSTG) * G_STAGE_B;
            const uint32_t sA = st;
            const uint32_t sW = st + G_ARR_B;

            #pragma unroll
            for (int ks = 0; ks < 4; ks++) {
                uint32_t af[2][4];
                #pragma unroll
                for (int mi = 0; mi < 2; mi++)
                    ldm_x4(af[mi], sA + swz128(rowA[mi], chA + ks * 2));
                uint32_t bf[4][4];
                #pragma unroll
                for (int p = 0; p < 4; p++)
                    ldm_x4(bf[p], sW + swz128(rowB[p], chB + ks * 2));
                #pragma unroll
                for (int mi = 0; mi < 2; mi++)
                    #pragma unroll
                    for (int p = 0; p < 4; p++)
                        #pragma unroll
                        for (int hf = 0; hf < 2; hf++)
                            mma_f16(acc[mi][p * 2 + hf], af[mi], &bf[p][hf * 2]);
            }
        }
        cp_wait<0>();   // drain tail empty groups before ring reuse next tile

        // --- epilogue ---
        const float* bias;
        __half* dst16 = nullptr;
        float scale = 1.f;
        if (MODE == 0) {
            if (z == 0)      { dst16 = g_q16; bias = b0; scale = QSCALE; }
            else if (z == 1) { dst16 = g_k16; bias = b1; }
            else             { dst16 = g_v16; bias = b2; }
        } else {
            bias = b0;
        }

        #pragma unroll
        for (int mi = 0; mi < 2; mi++) {
            #pragma unroll
            for (int ni = 0; ni < 8; ni++) {
                const int n0 = nBase + wn + ni * 8 + (lane & 3) * 2;
                const float bv0 = __ldg(bias + n0), bv1 = __ldg(bias + n0 + 1);
                #pragma unroll
                for (int rr = 0; rr < 2; rr++) {
                    const int m = mBase + wm + mi * 16 + (lane >> 2) + rr * 8;
                    float v0 = acc[mi][ni][rr * 2 + 0] + bv0;
                    float v1 = acc[mi][ni][rr * 2 + 1] + bv1;
                    if (MODE == 0) {
                        v0 *= scale; v1 *= scale;
                        const int bb = m >> 11, tt = m & 2047;
                        const int hh = n0 >> 6, hd = n0 & 63;
                        const size_t idx =
                            ((((size_t)bb * H_ + hh) * T_ + tt) << 6) + hd;
                        reinterpret_cast<uint32_t*>(dst16)[idx >> 1] =
                            packh2(v0, v1);
                    } else {
                        *reinterpret_cast<float2*>(out + (size_t)m * D_ + n0) =
                            make_float2(v0, v1);
                    }
                }
            }
        }
    }
}

// ---------------------------------------------------------------------------
// Tensor-core causal flash attention, pure f16 operands, fp32 accum.
// Q fragments register-resident, serial per-tile softmax with warp-uniform
// rescale skip, 6-stage KV ring, single sync per iteration, 2 CTAs/SM.
// ---------------------------------------------------------------------------
constexpr int ATT_ARR_B   = 64 * 128;                 // 8192 per array
constexpr int ATT_STAGE_B = 2 * ATT_ARR_B;            // 16384 (k, v)
constexpr int ATT_NSTG    = 6;
constexpr int ATT_SMEM    = ATT_NSTG * ATT_STAGE_B;   // 98304 -> 2 CTAs/SM

__global__ __launch_bounds__(256, 2)
void attn_mma()
{
    extern __shared__ __align__(128) char smem[];
    const uint32_t sb = smem_u32(smem);

    const int tid  = threadIdx.x;
    const int wid  = tid >> 5;
    const int lane = tid & 31;

    const int qb = (gridDim.x - 1) - blockIdx.x;     // largest-first
    const int h  = blockIdx.y, b = blockIdx.z;
    const size_t bh = ((size_t)(b * H_ + h)) * T_ * HD_;

    const __half* Q = g_q16 + bh + (size_t)qb * 128 * HD_;
    const __half* K = g_k16 + bh;
    const __half* V = g_v16 + bh;

    const int KT = 2 * qb + 2;   // >= 2

    // ---- Q via ring stage 0 (128 rows x 128B = 16KB), then to registers ----
    #pragma unroll
    for (int i = 0; i < 4; i++) {
        const int c = i * 256 + tid;
        const int row = c >> 3, q8 = c & 7;
        cp16(sb + swz128(row, q8), Q + (size_t)row * HD_ + q8 * 8);
    }
    cp_commit();
    cp_wait<0>();
    __syncthreads();

    uint32_t qf[4][4];
    {
        const int rowQ = wid * 16 + (lane & 7) + ((lane >> 3) & 1) * 8;
        const int chQ  = (lane >> 4) & 1;
        #pragma unroll
        for (int kc = 0; kc < 4; kc++)
            ldm_x4(qf[kc], sb + swz128(rowQ, chQ + kc * 2));
    }
    __syncthreads();             // all warps done reading Q smem

    auto load_kv = [&](int stg, int kt) {
        const uint32_t base = sb + stg * ATT_STAGE_B;
        #pragma unroll
        for (int i = 0; i < 4; i++) {                // 2 arrays * 512 chunks
            const int c = i * 256 + tid;
            const int arr = c >> 9, row = (c >> 3) & 63, q8 = c & 7;
            const __half* g = arr ? V : K;
            cp16(base + arr * ATT_ARR_B + swz128(row, q8),
                 g + (size_t)(kt * 64 + row) * HD_ + q8 * 8);
        }
        cp_commit();
    };
    // prologue: fill stages 0..4 (empty commits past KT)
    #pragma unroll
    for (int j = 0; j < 5; j++) {
        if (j < KT) load_kv(j, j);
        else        cp_commit();
    }

    float o[8][4];
    #pragma unroll
    for (int nt = 0; nt < 8; nt++)
        #pragma unroll
        for (int r = 0; r < 4; r++) o[nt][r] = 0.f;
    float m0 = -1e30f, m1 = -1e30f, l0 = 0.f, l1 = 0.f;

    const int r0g = qb * 128 + wid * 16 + (lane >> 2);

    const int rKbase = ((lane >> 4) & 1) * 8 + (lane & 7);
    const int chK    = (lane >> 3) & 1;
    const int rVbase = (lane & 7) + ((lane >> 3) & 1) * 8;
    const int chV    = (lane >> 4) & 1;

    const uint32_t ONES2[2] = {0x3C003C00u, 0x3C003C00u};

    #pragma unroll 1
    for (int kt = 0; kt < KT; kt++) {
        cp_wait<4>();            // stage kt ready
        __syncthreads();         // all warps done with stage kt-1

        if (kt + 5 < KT) load_kv((kt + 5) % ATT_NSTG, kt + 5);
        else             cp_commit();

        const uint32_t st  = sb + (kt % ATT_NSTG) * ATT_STAGE_B;
        const uint32_t stK = st;
        const uint32_t stV = st + ATT_ARR_B;

        // ---- S = q16 . k16 ----
        float s[8][4];
        #pragma unroll
        for (int nt = 0; nt < 8; nt++)
            #pragma unroll
            for (int r = 0; r < 4; r++) s[nt][r] = 0.f;

        #pragma unroll
        for (int kc = 0; kc < 4; kc++) {
            #pragma unroll
            for (int g = 0; g < 2; g++) {
                uint32_t kf[2][4];
                #pragma unroll
                for (int t = 0; t < 2; t++) {
                    const int nt16 = g * 2 + t;
                    ldm_x4(kf[t], stK + swz128(rKbase + nt16 * 16, chK + kc * 2));
                }
                #pragma unroll
                for (int t = 0; t < 2; t++)
                    #pragma unroll
                    for (int hf = 0; hf < 2; hf++)
                        mma_f16(s[(g * 2 + t) * 2 + hf], qf[kc], &kf[t][hf * 2]);
            }
        }

        // ---- causal mask (last two tiles only) ----
        if (kt >= KT - 2) {
            const int colBase = kt * 64 + (lane & 3) * 2;
            #pragma unroll
            for (int nt = 0; nt < 8; nt++)
                #pragma unroll
                for (int j = 0; j < 2; j++) {
                    const int c = colBase + nt * 8 + j;
                    if (c > r0g)     s[nt][j]     = -30000.f;
                    if (c > r0g + 8) s[nt][2 + j] = -30000.f;
                }
        }

        // ---- max-reduce; warp-uniform skip of o-rescale when no row updates
        float tm0 = -1e30f, tm1 = -1e30f;
        #pragma unroll
        for (int nt = 0; nt < 8; nt++) {
            tm0 = fmaxf(tm0, fmaxf(s[nt][0], s[nt][1]));
            tm1 = fmaxf(tm1, fmaxf(s[nt][2], s[nt][3]));
        }
        tm0 = fmaxf(tm0, __shfl_xor_sync(0xffffffffu, tm0, 1));
        tm0 = fmaxf(tm0, __shfl_xor_sync(0xffffffffu, tm0, 2));
        tm1 = fmaxf(tm1, __shfl_xor_sync(0xffffffffu, tm1, 1));
        tm1 = fmaxf(tm1, __shfl_xor_sync(0xffffffffu, tm1, 2));

        const float mn0 = fmaxf(m0, tm0), mn1 = fmaxf(m1, tm1);
        const bool noup = (mn0 == m0) && (mn1 == m1);
        float c0 = 1.f, c1 = 1.f;
        if (!__all_sync(0xffffffffu, noup)) {
            c0 = ex2f(m0 - mn0);
            c1 = ex2f(m1 - mn1);
            m0 = mn0; m1 = mn1;
            #pragma unroll
            for (int nt = 0; nt < 8; nt++) {
                o[nt][0] *= c0; o[nt][1] *= c0;
                o[nt][2] *= c1; o[nt][3] *= c1;
            }
        }

        // ---- P = ex2(S-m) f16; row sums via MMA; O += P V ----
        float dsum[4] = {0.f, 0.f, 0.f, 0.f};
        #pragma unroll
        for (int kc = 0; kc < 4; kc++) {
            const float* s0 = s[2 * kc];
            const float* s1 = s[2 * kc + 1];
            uint32_t ph[4];
            ph[0] = ex2h2(packh2(s0[0] - m0, s0[1] - m0));
            ph[1] = ex2h2(packh2(s0[2] - m1, s0[3] - m1));
            ph[2] = ex2h2(packh2(s1[0] - m0, s1[1] - m0));
            ph[3] = ex2h2(packh2(s1[2] - m1, s1[3] - m1));

            mma_f16(dsum, ph, ONES2);

            const int rowV = rVbase + kc * 16;
            #pragma unroll
            for (int nt16 = 0; nt16 < 4; nt16++) {
                uint32_t vf[4];
                ldm_x4_t(vf, stV + swz128(rowV, chV + nt16 * 2));
                #pragma unroll
                for (int hf = 0; hf < 2; hf++)
                    mma_f16(o[nt16 * 2 + hf], ph, &vf[hf * 2]);
            }
        }
        l0 = l0 * c0 + dsum[0];
        l1 = l1 * c1 + dsum[2];
    }

    // ---- finalize: single f16 plane out ----
    const float inv0 = 1.f / l0, inv1 = 1.f / l1;

    const size_t row0 = (size_t)b * T_ + qb * 128 + wid * 16 + (lane >> 2);
    const size_t row1 = row0 + 8;
    const int colB = h * HD_ + (lane & 3) * 2;

    #pragma unroll
    for (int nt = 0; nt < 8; nt++) {
        const size_t i0 = row0 * D_ + colB + nt * 8;
        const size_t i1 = row1 * D_ + colB + nt * 8;
        reinterpret_cast<uint32_t*>(g_o16)[i0 >> 1] =
            packh2(o[nt][0] * inv0, o[nt][1] * inv0);
        reinterpret_cast<uint32_t*>(g_o16)[i1 >> 1] =
            packh2(o[nt][2] * inv1, o[nt][3] * inv1);
    }
}

// ---------------------------------------------------------------------------
// Conversion kernels
// ---------------------------------------------------------------------------
__global__ __launch_bounds__(256) void quant_x_kernel(const float4* __restrict__ src)
{
    const int i = blockIdx.x * 256 + threadIdx.x;   // covers M_*D_/4
    const float4 v = src[i];
    uint2 r;
    r.x = packh2(v.x, v.y);
    r.y = packh2(v.z, v.w);
    reinterpret_cast<uint2*>(g_x16)[i] = r;
}

// transpose + quantize 4 weights; also resets persistent-GEMM counters
__global__ __launch_bounds__(256) void wquant_kernel(
    const float* __restrict__ wq, const float* __restrict__ wk,
    const float* __restrict__ wv, const float* __restrict__ wo)
{
    if (blockIdx.x == 0 && blockIdx.y == 0 && blockIdx.z == 0 &&
        threadIdx.x == 0) {
        g_ctr[0] = 0;
        g_ctr[1] = 0;
    }

    __shared__ float tile[32][33];
    const int z = blockIdx.z;
    const float* w = (z == 0) ? wq : (z == 1) ? wk : (z == 2) ? wv : wo;
    const int nB = blockIdx.x * 32, kB = blockIdx.y * 32;
    const int tx = threadIdx.x & 31, ty = threadIdx.x >> 5;

    #pragma unroll
    for (int r = ty; r < 32; r += 8)
        tile[r][tx] = w[(size_t)(kB + r) * D_ + nB + tx];
    __syncthreads();
    #pragma unroll
    for (int r = ty; r < 32; r += 8) {
        const size_t di = ((size_t)z << 20) + (size_t)(nB + r) * D_ + kB + tx;
        g_wt[di] = __float2half_rn(tile[tx][r]);
    }
}

// ---------------------------------------------------------------------------
extern "C" void kernel_launch(void* const* d_in, const int* in_sizes, int n_in,
                              void* d_out, int out_size)
{
    const float* x  = (const float*)d_in[0];
    const float* wq = (const float*)d_in[1];
    const float* bq = (const float*)d_in[2];
    const float* wk = (const float*)d_in[3];
    const float* bk = (const float*)d_in[4];
    const float* wv = (const float*)d_in[5];
    const float* bv = (const float*)d_in[6];
    const float* wo = (const float*)d_in[7];
    const float* bo = (const float*)d_in[8];
    float* out = (float*)d_out;

    static bool attrSet = false;
    if (!attrSet) {
        cudaFuncSetAttribute(gemm_mma<0>,
                             cudaFuncAttributeMaxDynamicSharedMemorySize, GEMM_SMEM);
        cudaFuncSetAttribute(gemm_mma<1>,
                             cudaFuncAttributeMaxDynamicSharedMemorySize, GEMM_SMEM);
        cudaFuncSetAttribute(attn_mma,
                             cudaFuncAttributeMaxDynamicSharedMemorySize, ATT_SMEM);
        attrSet = true;
    }

    void *px16, *po16;
    cudaGetSymbolAddress(&px16, g_x16);
    cudaGetSymbolAddress(&po16, g_o16);

    const int nElem = M_ * D_;

    // 1) convert inputs (wquant also resets the persistent tile counters)
    quant_x_kernel<<<nElem / 1024, 256>>>((const float4*)x);
    wquant_kernel<<<dim3(32, 32, 4), 256>>>(wq, wk, wv, wo);

    // 2) QKV projections (persistent, 1536 tiles) -> q/k/v f16 [B,H,T,HD]
    gemm_mma<0><<<GEMM_GRID, 256, GEMM_SMEM>>>(
        (const __half*)px16, bq, bk, bv, nullptr);

    // 3) tensor-core causal flash attention -> g_o16 [B*T, D]
    attn_mma<<<dim3(T_ / 128, H_, B_), 256, ATT_SMEM>>>();

    // 4) output projection (persistent, 512 tiles)
    gemm_mma<1><<<GEMM_GRID, 256, GEMM_SMEM>>>(
        (const __half*)po16, bo, nullptr, nullptr, out);
}

// round 15
// speedup vs baseline: 1.2728x; 1.0902x over previous
#include <cuda_runtime.h>
#include <cuda_fp16.h>
#include <cstdint>
#include <cstddef>

// ---------------------------------------------------------------------------
// Problem constants
// ---------------------------------------------------------------------------
constexpr int B_  = 4;
constexpr int T_  = 2048;
constexpr int D_  = 1024;
constexpr int H_  = 16;
constexpr int HD_ = 64;
constexpr int M_  = B_ * T_;   // 8192

// 0.125 * log2(e): folded into Q so softmax uses exp2
constexpr float QSCALE = 0.18033688011112042f;

// GB300: 152 SMs, 2 CTAs/SM
constexpr int PERSIST_GRID = 304;

// ---------------------------------------------------------------------------
// Device scratch (pure f16 pipeline, fp32 accumulation in-kernel)
// ---------------------------------------------------------------------------
__device__ __align__(128) __half g_x16[(size_t)M_ * D_];   // x f16
__device__ __align__(128) __half g_o16[(size_t)M_ * D_];   // attnO f16 [B*T, D]
__device__ __align__(128) __half g_q16[(size_t)M_ * D_];   // [B,H,T,HD]
__device__ __align__(128) __half g_k16[(size_t)M_ * D_];
__device__ __align__(128) __half g_v16[(size_t)M_ * D_];
// 4 weights transposed to [N, K] f16, z: 0..3 -> wq,wk,wv,wo
__device__ __align__(128) __half g_wt[(size_t)4 * D_ * D_];
// persistent tile counters: 0=QKV gemm, 1=O gemm, 2=attention
__device__ unsigned int g_ctr[3];

// ---------------------------------------------------------------------------
// PTX helpers
// ---------------------------------------------------------------------------
__device__ __forceinline__ uint32_t smem_u32(const void* p) {
    uint32_t a;
    asm("{ .reg .u64 t; cvta.to.shared.u64 t, %1; cvt.u32.u64 %0, t; }"
        : "=r"(a) : "l"(p));
    return a;
}
__device__ __forceinline__ void cp16(uint32_t saddr, const void* gaddr) {
    asm volatile("cp.async.cg.shared.global [%0], [%1], 16;"
                 :: "r"(saddr), "l"(gaddr));
}
__device__ __forceinline__ void cp_commit() {
    asm volatile("cp.async.commit_group;");
}
template <int N>
__device__ __forceinline__ void cp_wait() {
    asm volatile("cp.async.wait_group %0;" :: "n"(N));
}
__device__ __forceinline__ void ldm_x4(uint32_t* r, uint32_t addr) {
    asm volatile("ldmatrix.sync.aligned.m8n8.x4.shared.b16 {%0,%1,%2,%3}, [%4];"
                 : "=r"(r[0]), "=r"(r[1]), "=r"(r[2]), "=r"(r[3]) : "r"(addr));
}
__device__ __forceinline__ void ldm_x4_t(uint32_t* r, uint32_t addr) {
    asm volatile("ldmatrix.sync.aligned.m8n8.x4.trans.shared.b16 {%0,%1,%2,%3}, [%4];"
                 : "=r"(r[0]), "=r"(r[1]), "=r"(r[2]), "=r"(r[3]) : "r"(addr));
}
__device__ __forceinline__ void mma_f16(float* c, const uint32_t* a,
                                        const uint32_t* b) {
    asm volatile(
        "mma.sync.aligned.m16n8k16.row.col.f32.f16.f16.f32 "
        "{%0,%1,%2,%3}, {%4,%5,%6,%7}, {%8,%9}, {%0,%1,%2,%3};"
        : "+f"(c[0]), "+f"(c[1]), "+f"(c[2]), "+f"(c[3])
        : "r"(a[0]), "r"(a[1]), "r"(a[2]), "r"(a[3]), "r"(b[0]), "r"(b[1]));
}
__device__ __forceinline__ float ex2f(float x) {
    float r;
    asm("ex2.approx.ftz.f32 %0, %1;" : "=f"(r) : "f"(x));
    return r;
}
// packed f16x2: {low=lo, high=hi}
__device__ __forceinline__ uint32_t packh2(float lo, float hi) {
    uint32_t r;
    asm("cvt.rn.f16x2.f32 %0, %1, %2;" : "=r"(r) : "f"(hi), "f"(lo));
    return r;
}
__device__ __forceinline__ uint32_t ex2h2(uint32_t x) {
    uint32_t r;
    asm("ex2.approx.f16x2 %0, %1;" : "=r"(r) : "r"(x));
    return r;
}

// 128B-pitch SW128 swizzle: byte offset of (row, 16B-chunk)
__device__ __forceinline__ uint32_t swz128(int row, int chunk) {
    return (uint32_t)row * 128u + (uint32_t)((chunk ^ (row & 7)) << 4);
}

// ---------------------------------------------------------------------------
// Persistent HMMA GEMM, 1-term f16: C = A16 @ W16^T + bias, fp32 accum.
// grid = 304 CTAs (2/SM on 152 SMs), atomic tile counter; per tile: 8 warps
// (4Mx2N), warp 32x64, BK=64 (full SW128 rows), 3-stage 32KB ring.
// MODE 0: tiles z in {0,1,2} -> q/k/v f16 [B,H,T,HD]; Q pre-scaled.
// MODE 1: z = 3 -> out fp32 [M, D].
// ---------------------------------------------------------------------------
constexpr int BK        = 64;
constexpr int G_ARR_B   = 128 * 128;                  // 16384 B per tile array
constexpr int G_STAGE_B = 2 * G_ARR_B;                // 32768 (A, W)
constexpr int G_NSTG    = 3;
constexpr int GEMM_SMEM = G_NSTG * G_STAGE_B + 128;   // ring + control slot
constexpr int KT_G      = D_ / BK;                    // 16

template <int MODE>
__global__ __launch_bounds__(256, 2)
void gemm_mma(const __half* __restrict__ A,
              const float* __restrict__ b0, const float* __restrict__ b1,
              const float* __restrict__ b2,
              float* __restrict__ out)
{
    extern __shared__ __align__(128) char smem[];
    const uint32_t sb = smem_u32(smem);
    int* tileSlot = reinterpret_cast<int*>(smem + G_NSTG * G_STAGE_B);

    constexpr int NT = (MODE == 0) ? 1536 : 512;

    const int tid  = threadIdx.x;
    const int wid  = tid >> 5;
    const int lane = tid & 31;
    const int wm   = (wid & 3) * 32;
    const int wn   = (wid >> 2) * 64;

    int rowA[2], rowB[4];
    #pragma unroll
    for (int mi = 0; mi < 2; mi++)
        rowA[mi] = wm + (lane & 7) + ((lane >> 3) & 1) * 8 + mi * 16;
    #pragma unroll
    for (int p = 0; p < 4; p++)
        rowB[p] = wn + ((lane >> 4) & 1) * 8 + (lane & 7) + p * 16;
    const int chA = (lane >> 4) & 1;
    const int chB = (lane >> 3) & 1;

    for (;;) {
        __syncthreads();                   // ring + control safe to reuse
        if (tid == 0)
            *tileSlot = (int)atomicAdd(&g_ctr[MODE], 1u);
        __syncthreads();
        const int tile = *tileSlot;
        if (tile >= NT) break;

        const int z     = (MODE == 0) ? (tile >> 9) : 3;
        const int rem   = tile & 511;
        const int mBase = (rem >> 3) * 128;
        const int nBase = (rem & 7) * 128;
        const __half* W = g_wt + ((size_t)z << 20);

        auto load_stage = [&](int stg, int kt) {
            const uint32_t st = sb + stg * G_STAGE_B;
            const int bk = kt * BK;
            #pragma unroll
            for (int j = 0; j < 4; j++) {       // 1024 chunks per array
                const int c = j * 256 + tid;
                const int row = c >> 3, q8 = c & 7;
                const uint32_t off = swz128(row, q8);
                cp16(st + off,
                     A + (size_t)(mBase + row) * D_ + bk + q8 * 8);
                cp16(st + G_ARR_B + off,
                     W + (size_t)(nBase + row) * D_ + bk + q8 * 8);
            }
            cp_commit();
        };

        float acc[2][8][4];
        #pragma unroll
        for (int mi = 0; mi < 2; mi++)
            #pragma unroll
            for (int ni = 0; ni < 8; ni++)
                #pragma unroll
                for (int r = 0; r < 4; r++) acc[mi][ni][r] = 0.f;

        load_stage(0, 0);
        load_stage(1, 1);

        #pragma unroll 1
        for (int kt = 0; kt < KT_G; kt++) {
            cp_wait<1>();            // stage kt ready
            __syncthreads();         // all warps done with stage kt-1

            if (kt + 2 < KT_G) load_stage((kt + 2) % G_NSTG, kt + 2);
            else               cp_commit();

            const uint32_t st = sb + (kt % G_NSTG) * G_STAGE_B;
            const uint32_t sA = st;
            const uint32_t sW = st + G_ARR_B;

            #pragma unroll
            for (int ks = 0; ks < 4; ks++) {
                uint32_t af[2][4];
                #pragma unroll
                for (int mi = 0; mi < 2; mi++)
                    ldm_x4(af[mi], sA + swz128(rowA[mi], chA + ks * 2));
                uint32_t bf[4][4];
                #pragma unroll
                for (int p = 0; p < 4; p++)
                    ldm_x4(bf[p], sW + swz128(rowB[p], chB + ks * 2));
                #pragma unroll
                for (int mi = 0; mi < 2; mi++)
                    #pragma unroll
                    for (int p = 0; p < 4; p++)
                        #pragma unroll
                        for (int hf = 0; hf < 2; hf++)
                            mma_f16(acc[mi][p * 2 + hf], af[mi], &bf[p][hf * 2]);
            }
        }
        cp_wait<0>();   // drain tail empty groups before ring reuse next tile

        // --- epilogue ---
        const float* bias;
        __half* dst16 = nullptr;
        float scale = 1.f;
        if (MODE == 0) {
            if (z == 0)      { dst16 = g_q16; bias = b0; scale = QSCALE; }
            else if (z == 1) { dst16 = g_k16; bias = b1; }
            else             { dst16 = g_v16; bias = b2; }
        } else {
            bias = b0;
        }

        #pragma unroll
        for (int mi = 0; mi < 2; mi++) {
            #pragma unroll
            for (int ni = 0; ni < 8; ni++) {
                const int n0 = nBase + wn + ni * 8 + (lane & 3) * 2;
                const float bv0 = __ldg(bias + n0), bv1 = __ldg(bias + n0 + 1);
                #pragma unroll
                for (int rr = 0; rr < 2; rr++) {
                    const int m = mBase + wm + mi * 16 + (lane >> 2) + rr * 8;
                    float v0 = acc[mi][ni][rr * 2 + 0] + bv0;
                    float v1 = acc[mi][ni][rr * 2 + 1] + bv1;
                    if (MODE == 0) {
                        v0 *= scale; v1 *= scale;
                        const int bb = m >> 11, tt = m & 2047;
                        const int hh = n0 >> 6, hd = n0 & 63;
                        const size_t idx =
                            ((((size_t)bb * H_ + hh) * T_ + tt) << 6) + hd;
                        reinterpret_cast<uint32_t*>(dst16)[idx >> 1] =
                            packh2(v0, v1);
                    } else {
                        *reinterpret_cast<float2*>(out + (size_t)m * D_ + n0) =
                            make_float2(v0, v1);
                    }
                }
            }
        }
    }
}

// ---------------------------------------------------------------------------
// Persistent tensor-core causal flash attention, pure f16, fp32 accum.
// grid = 304; items sorted largest-qb-first via atomic counter (greedy LPT
// balance, no wave quantization). Per item: Q fragments register-resident,
// serial per-tile softmax, 6-stage KV ring, single sync per iteration.
// ---------------------------------------------------------------------------
constexpr int ATT_ARR_B   = 64 * 128;                 // 8192 per array
constexpr int ATT_STAGE_B = 2 * ATT_ARR_B;            // 16384 (k, v)
constexpr int ATT_NSTG    = 6;
constexpr int ATT_SMEM    = ATT_NSTG * ATT_STAGE_B + 128;  // ring + control
constexpr int ATT_ITEMS   = (T_ / 128) * H_ * B_;     // 1024

__global__ __launch_bounds__(256, 2)
void attn_mma()
{
    extern __shared__ __align__(128) char smem[];
    const uint32_t sb = smem_u32(smem);
    int* itemSlot = reinterpret_cast<int*>(smem + ATT_NSTG * ATT_STAGE_B);

    const int tid  = threadIdx.x;
    const int wid  = tid >> 5;
    const int lane = tid & 31;

    const int rKbase = ((lane >> 4) & 1) * 8 + (lane & 7);
    const int chK    = (lane >> 3) & 1;
    const int rVbase = (lane & 7) + ((lane >> 3) & 1) * 8;
    const int chV    = (lane >> 4) & 1;
    const uint32_t ONES2[2] = {0x3C003C00u, 0x3C003C00u};

    for (;;) {
        __syncthreads();                 // ring + control safe to reuse
        if (tid == 0)
            *itemSlot = (int)atomicAdd(&g_ctr[2], 1u);
        __syncthreads();
        const int item = *itemSlot;
        if (item >= ATT_ITEMS) break;

        // largest-qb-first ordering
        const int qb   = (T_ / 128 - 1) - (item >> 6);
        const int bhid = item & 63;
        const int b    = bhid >> 4;
        const int h    = bhid & 15;
        const size_t bh = ((size_t)(b * H_ + h)) * T_ * HD_;

        const __half* Q = g_q16 + bh + (size_t)qb * 128 * HD_;
        const __half* K = g_k16 + bh;
        const __half* V = g_v16 + bh;

        const int KT = 2 * qb + 2;   // >= 2

        // ---- Q via ring stage 0, then to registers ----
        #pragma unroll
        for (int i = 0; i < 4; i++) {
            const int c = i * 256 + tid;
            const int row = c >> 3, q8 = c & 7;
            cp16(sb + swz128(row, q8), Q + (size_t)row * HD_ + q8 * 8);
        }
        cp_commit();
        cp_wait<0>();
        __syncthreads();

        uint32_t qf[4][4];
        {
            const int rowQ = wid * 16 + (lane & 7) + ((lane >> 3) & 1) * 8;
            const int chQ  = (lane >> 4) & 1;
            #pragma unroll
            for (int kc = 0; kc < 4; kc++)
                ldm_x4(qf[kc], sb + swz128(rowQ, chQ + kc * 2));
        }
        __syncthreads();             // all warps done reading Q smem

        auto load_kv = [&](int stg, int kt) {
            const uint32_t base = sb + stg * ATT_STAGE_B;
            #pragma unroll
            for (int i = 0; i < 4; i++) {            // 2 arrays * 512 chunks
                const int c = i * 256 + tid;
                const int arr = c >> 9, row = (c >> 3) & 63, q8 = c & 7;
                const __half* g = arr ? V : K;
                cp16(base + arr * ATT_ARR_B + swz128(row, q8),
                     g + (size_t)(kt * 64 + row) * HD_ + q8 * 8);
            }
            cp_commit();
        };
        // prologue: fill stages 0..4 (empty commits past KT)
        #pragma unroll
        for (int j = 0; j < 5; j++) {
            if (j < KT) load_kv(j, j);
            else        cp_commit();
        }

        float o[8][4];
        #pragma unroll
        for (int nt = 0; nt < 8; nt++)
            #pragma unroll
            for (int r = 0; r < 4; r++) o[nt][r] = 0.f;
        float m0 = -1e30f, m1 = -1e30f, l0 = 0.f, l1 = 0.f;

        const int r0g = qb * 128 + wid * 16 + (lane >> 2);

        #pragma unroll 1
        for (int kt = 0; kt < KT; kt++) {
            cp_wait<4>();            // stage kt ready
            __syncthreads();         // all warps done with stage kt-1

            if (kt + 5 < KT) load_kv((kt + 5) % ATT_NSTG, kt + 5);
            else             cp_commit();

            const uint32_t st  = sb + (kt % ATT_NSTG) * ATT_STAGE_B;
            const uint32_t stK = st;
            const uint32_t stV = st + ATT_ARR_B;

            // ---- S = q16 . k16 ----
            float s[8][4];
            #pragma unroll
            for (int nt = 0; nt < 8; nt++)
                #pragma unroll
                for (int r = 0; r < 4; r++) s[nt][r] = 0.f;

            #pragma unroll
            for (int kc = 0; kc < 4; kc++) {
                #pragma unroll
                for (int g = 0; g < 2; g++) {
                    uint32_t kf[2][4];
                    #pragma unroll
                    for (int t = 0; t < 2; t++) {
                        const int nt16 = g * 2 + t;
                        ldm_x4(kf[t],
                               stK + swz128(rKbase + nt16 * 16, chK + kc * 2));
                    }
                    #pragma unroll
                    for (int t = 0; t < 2; t++)
                        #pragma unroll
                        for (int hf = 0; hf < 2; hf++)
                            mma_f16(s[(g * 2 + t) * 2 + hf], qf[kc],
                                    &kf[t][hf * 2]);
                }
            }

            // ---- causal mask (last two tiles only) ----
            if (kt >= KT - 2) {
                const int colBase = kt * 64 + (lane & 3) * 2;
                #pragma unroll
                for (int nt = 0; nt < 8; nt++)
                    #pragma unroll
                    for (int j = 0; j < 2; j++) {
                        const int c = colBase + nt * 8 + j;
                        if (c > r0g)     s[nt][j]     = -30000.f;
                        if (c > r0g + 8) s[nt][2 + j] = -30000.f;
                    }
            }

            // ---- max-reduce; warp-uniform skip of o-rescale ----
            float tm0 = -1e30f, tm1 = -1e30f;
            #pragma unroll
            for (int nt = 0; nt < 8; nt++) {
                tm0 = fmaxf(tm0, fmaxf(s[nt][0], s[nt][1]));
                tm1 = fmaxf(tm1, fmaxf(s[nt][2], s[nt][3]));
            }
            tm0 = fmaxf(tm0, __shfl_xor_sync(0xffffffffu, tm0, 1));
            tm0 = fmaxf(tm0, __shfl_xor_sync(0xffffffffu, tm0, 2));
            tm1 = fmaxf(tm1, __shfl_xor_sync(0xffffffffu, tm1, 1));
            tm1 = fmaxf(tm1, __shfl_xor_sync(0xffffffffu, tm1, 2));

            const float mn0 = fmaxf(m0, tm0), mn1 = fmaxf(m1, tm1);
            const bool noup = (mn0 == m0) && (mn1 == m1);
            float c0 = 1.f, c1 = 1.f;
            if (!__all_sync(0xffffffffu, noup)) {
                c0 = ex2f(m0 - mn0);
                c1 = ex2f(m1 - mn1);
                m0 = mn0; m1 = mn1;
                #pragma unroll
                for (int nt = 0; nt < 8; nt++) {
                    o[nt][0] *= c0; o[nt][1] *= c0;
                    o[nt][2] *= c1; o[nt][3] *= c1;
                }
            }

            // ---- P = ex2(S-m) f16; row sums via MMA; O += P V ----
            float dsum[4] = {0.f, 0.f, 0.f, 0.f};
            #pragma unroll
            for (int kc = 0; kc < 4; kc++) {
                const float* s0 = s[2 * kc];
                const float* s1 = s[2 * kc + 1];
                uint32_t ph[4];
                ph[0] = ex2h2(packh2(s0[0] - m0, s0[1] - m0));
                ph[1] = ex2h2(packh2(s0[2] - m1, s0[3] - m1));
                ph[2] = ex2h2(packh2(s1[0] - m0, s1[1] - m0));
                ph[3] = ex2h2(packh2(s1[2] - m1, s1[3] - m1));

                mma_f16(dsum, ph, ONES2);

                const int rowV = rVbase + kc * 16;
                #pragma unroll
                for (int nt16 = 0; nt16 < 4; nt16++) {
                    uint32_t vf[4];
                    ldm_x4_t(vf, stV + swz128(rowV, chV + nt16 * 2));
                    #pragma unroll
                    for (int hf = 0; hf < 2; hf++)
                        mma_f16(o[nt16 * 2 + hf], ph, &vf[hf * 2]);
                }
            }
            l0 = l0 * c0 + dsum[0];
            l1 = l1 * c1 + dsum[2];
        }
        cp_wait<0>();   // drain tail empties before ring reuse (next item)

        // ---- finalize: single f16 plane out ----
        const float inv0 = 1.f / l0, inv1 = 1.f / l1;

        const size_t row0 = (size_t)b * T_ + qb * 128 + wid * 16 + (lane >> 2);
        const size_t row1 = row0 + 8;
        const int colB = h * HD_ + (lane & 3) * 2;

        #pragma unroll
        for (int nt = 0; nt < 8; nt++) {
            const size_t i0 = row0 * D_ + colB + nt * 8;
            const size_t i1 = row1 * D_ + colB + nt * 8;
            reinterpret_cast<uint32_t*>(g_o16)[i0 >> 1] =
                packh2(o[nt][0] * inv0, o[nt][1] * inv0);
            reinterpret_cast<uint32_t*>(g_o16)[i1 >> 1] =
                packh2(o[nt][2] * inv1, o[nt][3] * inv1);
        }
    }
}

// ---------------------------------------------------------------------------
// Fused convert kernel: z in 0..3 -> transpose+quantize weight z;
// z == 4 -> quantize x (f32 -> f16, vectorized). Also resets tile counters.
// ---------------------------------------------------------------------------
__global__ __launch_bounds__(256) void convert_kernel(
    const float* __restrict__ wq, const float* __restrict__ wk,
    const float* __restrict__ wv, const float* __restrict__ wo,
    const float4* __restrict__ x)
{
    const int z = blockIdx.z;

    if (z == 4) {
        // x quant: 1024 blocks x 256 threads x 8 float4 = 8M floats
        const int bid  = blockIdx.y * 32 + blockIdx.x;
        const int base = bid * 256 + threadIdx.x;
        #pragma unroll
        for (int k = 0; k < 8; k++) {
            const int i = base + k * (1024 * 256);
            const float4 v = x[i];
            uint2 r;
            r.x = packh2(v.x, v.y);
            r.y = packh2(v.z, v.w);
            reinterpret_cast<uint2*>(g_x16)[i] = r;
        }
        return;
    }

    if (z == 0 && blockIdx.x == 0 && blockIdx.y == 0 && threadIdx.x == 0) {
        g_ctr[0] = 0;
        g_ctr[1] = 0;
        g_ctr[2] = 0;
    }

    __shared__ float tile[32][33];
    const float* w = (z == 0) ? wq : (z == 1) ? wk : (z == 2) ? wv : wo;
    const int nB = blockIdx.x * 32, kB = blockIdx.y * 32;
    const int tx = threadIdx.x & 31, ty = threadIdx.x >> 5;

    #pragma unroll
    for (int r = ty; r < 32; r += 8)
        tile[r][tx] = w[(size_t)(kB + r) * D_ + nB + tx];
    __syncthreads();
    #pragma unroll
    for (int r = ty; r < 32; r += 8) {
        const size_t di = ((size_t)z << 20) + (size_t)(nB + r) * D_ + kB + tx;
        g_wt[di] = __float2half_rn(tile[tx][r]);
    }
}

// ---------------------------------------------------------------------------
extern "C" void kernel_launch(void* const* d_in, const int* in_sizes, int n_in,
                              void* d_out, int out_size)
{
    const float* x  = (const float*)d_in[0];
    const float* wq = (const float*)d_in[1];
    const float* bq = (const float*)d_in[2];
    const float* wk = (const float*)d_in[3];
    const float* bk = (const float*)d_in[4];
    const float* wv = (const float*)d_in[5];
    const float* bv = (const float*)d_in[6];
    const float* wo = (const float*)d_in[7];
    const float* bo = (const float*)d_in[8];
    float* out = (float*)d_out;

    static bool attrSet = false;
    if (!attrSet) {
        cudaFuncSetAttribute(gemm_mma<0>,
                             cudaFuncAttributeMaxDynamicSharedMemorySize, GEMM_SMEM);
        cudaFuncSetAttribute(gemm_mma<1>,
                             cudaFuncAttributeMaxDynamicSharedMemorySize, GEMM_SMEM);
        cudaFuncSetAttribute(attn_mma,
                             cudaFuncAttributeMaxDynamicSharedMemorySize, ATT_SMEM);
        attrSet = true;
    }

    void *px16, *po16;
    cudaGetSymbolAddress(&px16, g_x16);
    cudaGetSymbolAddress(&po16, g_o16);

    // 1) converts (also resets the persistent counters)
    convert_kernel<<<dim3(32, 32, 5), 256>>>(wq, wk, wv, wo, (const float4*)x);

    // 2) QKV projections (persistent, 1536 tiles) -> q/k/v f16 [B,H,T,HD]
    gemm_mma<0><<<PERSIST_GRID, 256, GEMM_SMEM>>>(
        (const __half*)px16, bq, bk, bv, nullptr);

    // 3) persistent causal flash attention -> g_o16 [B*T, D]
    attn_mma<<<PERSIST_GRID, 256, ATT_SMEM>>>();

    // 4) output projection (persistent, 512 tiles)
    gemm_mma<1><<<PERSIST_GRID, 256, GEMM_SMEM>>>(
        (const __half*)po16, bo, nullptr, nullptr, out);
}

// round 16
// speedup vs baseline: 1.2871x; 1.0112x over previous
#include <cuda_runtime.h>
#include <cuda_fp16.h>
#include <cstdint>
#include <cstddef>

// ---------------------------------------------------------------------------
// Problem constants
// ---------------------------------------------------------------------------
constexpr int B_  = 4;
constexpr int T_  = 2048;
constexpr int D_  = 1024;
constexpr int H_  = 16;
constexpr int HD_ = 64;
constexpr int M_  = B_ * T_;   // 8192

// 0.125 * log2(e): folded into Q so softmax uses exp2
constexpr float QSCALE = 0.18033688011112042f;

// GB300: 152 SMs, 2 CTAs/SM
constexpr int PERSIST_GRID = 304;

// ---------------------------------------------------------------------------
// Device scratch (pure f16 pipeline, fp32 accumulation in-kernel)
// ---------------------------------------------------------------------------
__device__ __align__(128) __half g_x16[(size_t)M_ * D_];   // x f16
__device__ __align__(128) __half g_o16[(size_t)M_ * D_];   // attnO f16 [B*T, D]
__device__ __align__(128) __half g_q16[(size_t)M_ * D_];   // [B,H,T,HD]
__device__ __align__(128) __half g_k16[(size_t)M_ * D_];
__device__ __align__(128) __half g_v16[(size_t)M_ * D_];
// 4 weights transposed to [N, K] f16, z: 0..3 -> wq,wk,wv,wo
__device__ __align__(128) __half g_wt[(size_t)4 * D_ * D_];
// persistent tile counters: 0=QKV gemm, 1=O gemm, 2=attention
__device__ unsigned int g_ctr[3];

// ---------------------------------------------------------------------------
// PTX helpers
// ---------------------------------------------------------------------------
__device__ __forceinline__ uint32_t smem_u32(const void* p) {
    uint32_t a;
    asm("{ .reg .u64 t; cvta.to.shared.u64 t, %1; cvt.u32.u64 %0, t; }"
        : "=r"(a) : "l"(p));
    return a;
}
__device__ __forceinline__ void cp16(uint32_t saddr, const void* gaddr) {
    asm volatile("cp.async.cg.shared.global [%0], [%1], 16;"
                 :: "r"(saddr), "l"(gaddr));
}
__device__ __forceinline__ void cp_commit() {
    asm volatile("cp.async.commit_group;");
}
template <int N>
__device__ __forceinline__ void cp_wait() {
    asm volatile("cp.async.wait_group %0;" :: "n"(N));
}
__device__ __forceinline__ void ldm_x4(uint32_t* r, uint32_t addr) {
    asm volatile("ldmatrix.sync.aligned.m8n8.x4.shared.b16 {%0,%1,%2,%3}, [%4];"
                 : "=r"(r[0]), "=r"(r[1]), "=r"(r[2]), "=r"(r[3]) : "r"(addr));
}
__device__ __forceinline__ void ldm_x4_t(uint32_t* r, uint32_t addr) {
    asm volatile("ldmatrix.sync.aligned.m8n8.x4.trans.shared.b16 {%0,%1,%2,%3}, [%4];"
                 : "=r"(r[0]), "=r"(r[1]), "=r"(r[2]), "=r"(r[3]) : "r"(addr));
}
__device__ __forceinline__ void mma_f16(float* c, const uint32_t* a,
                                        const uint32_t* b) {
    asm volatile(
        "mma.sync.aligned.m16n8k16.row.col.f32.f16.f16.f32 "
        "{%0,%1,%2,%3}, {%4,%5,%6,%7}, {%8,%9}, {%0,%1,%2,%3};"
        : "+f"(c[0]), "+f"(c[1]), "+f"(c[2]), "+f"(c[3])
        : "r"(a[0]), "r"(a[1]), "r"(a[2]), "r"(a[3]), "r"(b[0]), "r"(b[1]));
}
__device__ __forceinline__ float ex2f(float x) {
    float r;
    asm("ex2.approx.ftz.f32 %0, %1;" : "=f"(r) : "f"(x));
    return r;
}
// packed f16x2: {low=lo, high=hi}
__device__ __forceinline__ uint32_t packh2(float lo, float hi) {
    uint32_t r;
    asm("cvt.rn.f16x2.f32 %0, %1, %2;" : "=r"(r) : "f"(hi), "f"(lo));
    return r;
}
__device__ __forceinline__ uint32_t ex2h2(uint32_t x) {
    uint32_t r;
    asm("ex2.approx.f16x2 %0, %1;" : "=r"(r) : "r"(x));
    return r;
}

// 128B-pitch SW128 swizzle: byte offset of (row, 16B-chunk)
__device__ __forceinline__ uint32_t swz128(int row, int chunk) {
    return (uint32_t)row * 128u + (uint32_t)((chunk ^ (row & 7)) << 4);
}

// ---------------------------------------------------------------------------
// Persistent HMMA GEMM, 1-term f16: C = A16 @ W16^T + bias, fp32 accum.
// grid = 304 CTAs (2/SM on 152 SMs), atomic tile counter; per tile: 8 warps
// (4Mx2N), warp 32x64, BK=64 (full SW128 rows), 3-stage 32KB ring.
// MODE 0: tiles z in {0,1,2} -> q/k/v f16 [B,H,T,HD]; Q pre-scaled.
// MODE 1: z = 3 -> out fp32 [M, D].
// ---------------------------------------------------------------------------
constexpr int BK        = 64;
constexpr int G_ARR_B   = 128 * 128;                  // 16384 B per tile array
constexpr int G_STAGE_B = 2 * G_ARR_B;                // 32768 (A, W)
constexpr int G_NSTG    = 3;
constexpr int GEMM_SMEM = G_NSTG * G_STAGE_B + 128;   // ring + control slot
constexpr int KT_G      = D_ / BK;                    // 16

template <int MODE>
__global__ __launch_bounds__(256, 2)
void gemm_mma(const __half* __restrict__ A,
              const float* __restrict__ b0, const float* __restrict__ b1,
              const float* __restrict__ b2,
              float* __restrict__ out)
{
    extern __shared__ __align__(128) char smem[];
    const uint32_t sb = smem_u32(smem);
    int* tileSlot = reinterpret_cast<int*>(smem + G_NSTG * G_STAGE_B);

    constexpr int NT = (MODE == 0) ? 1536 : 512;

    const int tid  = threadIdx.x;
    const int wid  = tid >> 5;
    const int lane = tid & 31;
    const int wm   = (wid & 3) * 32;
    const int wn   = (wid >> 2) * 64;

    int rowA[2], rowB[4];
    #pragma unroll
    for (int mi = 0; mi < 2; mi++)
        rowA[mi] = wm + (lane & 7) + ((lane >> 3) & 1) * 8 + mi * 16;
    #pragma unroll
    for (int p = 0; p < 4; p++)
        rowB[p] = wn + ((lane >> 4) & 1) * 8 + (lane & 7) + p * 16;
    const int chA = (lane >> 4) & 1;
    const int chB = (lane >> 3) & 1;

    for (;;) {
        __syncthreads();                   // ring + control safe to reuse
        if (tid == 0)
            *tileSlot = (int)atomicAdd(&g_ctr[MODE], 1u);
        __syncthreads();
        const int tile = *tileSlot;
        if (tile >= NT) break;

        const int z     = (MODE == 0) ? (tile >> 9) : 3;
        const int rem   = tile & 511;
        const int mBase = (rem >> 3) * 128;
        const int nBase = (rem & 7) * 128;
        const __half* W = g_wt + ((size_t)z << 20);

        auto load_stage = [&](int stg, int kt) {
            const uint32_t st = sb + stg * G_STAGE_B;
            const int bk = kt * BK;
            #pragma unroll
            for (int j = 0; j < 4; j++) {       // 1024 chunks per array
                const int c = j * 256 + tid;
                const int row = c >> 3, q8 = c & 7;
                const uint32_t off = swz128(row, q8);
                cp16(st + off,
                     A + (size_t)(mBase + row) * D_ + bk + q8 * 8);
                cp16(st + G_ARR_B + off,
                     W + (size_t)(nBase + row) * D_ + bk + q8 * 8);
            }
            cp_commit();
        };

        float acc[2][8][4];
        #pragma unroll
        for (int mi = 0; mi < 2; mi++)
            #pragma unroll
            for (int ni = 0; ni < 8; ni++)
                #pragma unroll
                for (int r = 0; r < 4; r++) acc[mi][ni][r] = 0.f;

        load_stage(0, 0);
        load_stage(1, 1);

        #pragma unroll 1
        for (int kt = 0; kt < KT_G; kt++) {
            cp_wait<1>();            // stage kt ready
            __syncthreads();         // all warps done with stage kt-1

            if (kt + 2 < KT_G) load_stage((kt + 2) % G_NSTG, kt + 2);
            else               cp_commit();

            const uint32_t st = sb + (kt % G_NSTG) * G_STAGE_B;
            const uint32_t sA = st;
            const uint32_t sW = st + G_ARR_B;

            #pragma unroll
            for (int ks = 0; ks < 4; ks++) {
                uint32_t af[2][4];
                #pragma unroll
                for (int mi = 0; mi < 2; mi++)
                    ldm_x4(af[mi], sA + swz128(rowA[mi], chA + ks * 2));
                uint32_t bf[4][4];
                #pragma unroll
                for (int p = 0; p < 4; p++)
                    ldm_x4(bf[p], sW + swz128(rowB[p], chB + ks * 2));
                #pragma unroll
                for (int mi = 0; mi < 2; mi++)
                    #pragma unroll
                    for (int p = 0; p < 4; p++)
                        #pragma unroll
                        for (int hf = 0; hf < 2; hf++)
                            mma_f16(acc[mi][p * 2 + hf], af[mi], &bf[p][hf * 2]);
            }
        }
        cp_wait<0>();   // drain tail empty groups before ring reuse next tile

        // --- epilogue ---
        const float* bias;
        __half* dst16 = nullptr;
        float scale = 1.f;
        if (MODE == 0) {
            if (z == 0)      { dst16 = g_q16; bias = b0; scale = QSCALE; }
            else if (z == 1) { dst16 = g_k16; bias = b1; }
            else             { dst16 = g_v16; bias = b2; }
        } else {
            bias = b0;
        }

        #pragma unroll
        for (int mi = 0; mi < 2; mi++) {
            #pragma unroll
            for (int ni = 0; ni < 8; ni++) {
                const int n0 = nBase + wn + ni * 8 + (lane & 3) * 2;
                const float bv0 = __ldg(bias + n0), bv1 = __ldg(bias + n0 + 1);
                #pragma unroll
                for (int rr = 0; rr < 2; rr++) {
                    const int m = mBase + wm + mi * 16 + (lane >> 2) + rr * 8;
                    float v0 = acc[mi][ni][rr * 2 + 0] + bv0;
                    float v1 = acc[mi][ni][rr * 2 + 1] + bv1;
                    if (MODE == 0) {
                        v0 *= scale; v1 *= scale;
                        const int bb = m >> 11, tt = m & 2047;
                        const int hh = n0 >> 6, hd = n0 & 63;
                        const size_t idx =
                            ((((size_t)bb * H_ + hh) * T_ + tt) << 6) + hd;
                        reinterpret_cast<uint32_t*>(dst16)[idx >> 1] =
                            packh2(v0, v1);
                    } else {
                        *reinterpret_cast<float2*>(out + (size_t)m * D_ + n0) =
                            make_float2(v0, v1);
                    }
                }
            }
        }
    }
}

// ---------------------------------------------------------------------------
// Persistent tensor-core causal flash attention, pure f16, fp32 accum.
// grid = 304; largest-qb-first via atomic counter. KV tile = 128 keys
// (processed as two 64-key halves; numerics identical to 64-key tiles).
// 3-stage 32KB KV ring, single sync per 128-key tile, 2 CTAs/SM.
// ---------------------------------------------------------------------------
constexpr int ATT_HALF_B  = 64 * 128;                 // 8192: 64 rows x 128B
constexpr int ATT_K_B     = 2 * ATT_HALF_B;           // K: 128 rows
constexpr int ATT_STAGE_B = 2 * ATT_K_B;              // 32768 (K128, V128)
constexpr int ATT_NSTG    = 3;
constexpr int ATT_SMEM    = ATT_NSTG * ATT_STAGE_B + 128;  // ring + control
constexpr int ATT_ITEMS   = (T_ / 128) * H_ * B_;     // 1024

__global__ __launch_bounds__(256, 2)
void attn_mma()
{
    extern __shared__ __align__(128) char smem[];
    const uint32_t sb = smem_u32(smem);
    int* itemSlot = reinterpret_cast<int*>(smem + ATT_NSTG * ATT_STAGE_B);

    const int tid  = threadIdx.x;
    const int wid  = tid >> 5;
    const int lane = tid & 31;

    const int rKbase = ((lane >> 4) & 1) * 8 + (lane & 7);
    const int chK    = (lane >> 3) & 1;
    const int rVbase = (lane & 7) + ((lane >> 3) & 1) * 8;
    const int chV    = (lane >> 4) & 1;
    const uint32_t ONES2[2] = {0x3C003C00u, 0x3C003C00u};

    for (;;) {
        __syncthreads();                 // ring + control safe to reuse
        if (tid == 0)
            *itemSlot = (int)atomicAdd(&g_ctr[2], 1u);
        __syncthreads();
        const int item = *itemSlot;
        if (item >= ATT_ITEMS) break;

        // largest-qb-first ordering
        const int qb   = (T_ / 128 - 1) - (item >> 6);
        const int bhid = item & 63;
        const int b    = bhid >> 4;
        const int h    = bhid & 15;
        const size_t bh = ((size_t)(b * H_ + h)) * T_ * HD_;

        const __half* Q = g_q16 + bh + (size_t)qb * 128 * HD_;
        const __half* K = g_k16 + bh;
        const __half* V = g_v16 + bh;

        const int KT = qb + 1;       // 128-key tiles, >= 1

        // ---- Q via ring stage 0, then to registers ----
        #pragma unroll
        for (int i = 0; i < 4; i++) {
            const int c = i * 256 + tid;
            const int row = c >> 3, q8 = c & 7;
            cp16(sb + swz128(row, q8), Q + (size_t)row * HD_ + q8 * 8);
        }
        cp_commit();
        cp_wait<0>();
        __syncthreads();

        uint32_t qf[4][4];
        {
            const int rowQ = wid * 16 + (lane & 7) + ((lane >> 3) & 1) * 8;
            const int chQ  = (lane >> 4) & 1;
            #pragma unroll
            for (int kc = 0; kc < 4; kc++)
                ldm_x4(qf[kc], sb + swz128(rowQ, chQ + kc * 2));
        }
        __syncthreads();             // all warps done reading Q smem

        auto load_kv = [&](int stg, int kt) {
            const uint32_t base = sb + stg * ATT_STAGE_B;
            #pragma unroll
            for (int i = 0; i < 8; i++) {            // 2 arrays * 1024 chunks
                const int c = i * 256 + tid;
                const int arr = c >> 10, row = (c >> 3) & 127, q8 = c & 7;
                const __half* g = arr ? V : K;
                cp16(base + arr * ATT_K_B + swz128(row, q8),
                     g + (size_t)(kt * 128 + row) * HD_ + q8 * 8);
            }
            cp_commit();
        };
        // prologue: fill stages 0..1 (empty commits past KT)
        #pragma unroll
        for (int j = 0; j < 2; j++) {
            if (j < KT) load_kv(j, j);
            else        cp_commit();
        }

        float o[8][4];
        #pragma unroll
        for (int nt = 0; nt < 8; nt++)
            #pragma unroll
            for (int r = 0; r < 4; r++) o[nt][r] = 0.f;
        float m0 = -1e30f, m1 = -1e30f, l0 = 0.f, l1 = 0.f;

        const int r0g = qb * 128 + wid * 16 + (lane >> 2);

        #pragma unroll 1
        for (int kt = 0; kt < KT; kt++) {
            cp_wait<1>();            // stage kt ready
            __syncthreads();         // all warps done with stage kt-1

            if (kt + 2 < KT) load_kv((kt + 2) % ATT_NSTG, kt + 2);
            else             cp_commit();

            const uint32_t st = sb + (kt % ATT_NSTG) * ATT_STAGE_B;
            const bool diag = (kt == KT - 1);

            #pragma unroll
            for (int half = 0; half < 2; half++) {
                const uint32_t stK = st + half * ATT_HALF_B;
                const uint32_t stV = st + ATT_K_B + half * ATT_HALF_B;

                // ---- S = q16 . k16 (64-key half) ----
                float s[8][4];
                #pragma unroll
                for (int nt = 0; nt < 8; nt++)
                    #pragma unroll
                    for (int r = 0; r < 4; r++) s[nt][r] = 0.f;

                #pragma unroll
                for (int kc = 0; kc < 4; kc++) {
                    #pragma unroll
                    for (int g = 0; g < 2; g++) {
                        uint32_t kf[2][4];
                        #pragma unroll
                        for (int t = 0; t < 2; t++) {
                            const int nt16 = g * 2 + t;
                            ldm_x4(kf[t], stK + swz128(rKbase + nt16 * 16,
                                                       chK + kc * 2));
                        }
                        #pragma unroll
                        for (int t = 0; t < 2; t++)
                            #pragma unroll
                            for (int hf = 0; hf < 2; hf++)
                                mma_f16(s[(g * 2 + t) * 2 + hf], qf[kc],
                                        &kf[t][hf * 2]);
                    }
                }

                // ---- causal mask (diagonal tile only) ----
                if (diag) {
                    const int colBase = kt * 128 + half * 64 + (lane & 3) * 2;
                    #pragma unroll
                    for (int nt = 0; nt < 8; nt++)
                        #pragma unroll
                        for (int j = 0; j < 2; j++) {
                            const int c = colBase + nt * 8 + j;
                            if (c > r0g)     s[nt][j]     = -30000.f;
                            if (c > r0g + 8) s[nt][2 + j] = -30000.f;
                        }
                }

                // ---- max-reduce; warp-uniform skip of o-rescale ----
                float tm0 = -1e30f, tm1 = -1e30f;
                #pragma unroll
                for (int nt = 0; nt < 8; nt++) {
                    tm0 = fmaxf(tm0, fmaxf(s[nt][0], s[nt][1]));
                    tm1 = fmaxf(tm1, fmaxf(s[nt][2], s[nt][3]));
                }
                tm0 = fmaxf(tm0, __shfl_xor_sync(0xffffffffu, tm0, 1));
                tm0 = fmaxf(tm0, __shfl_xor_sync(0xffffffffu, tm0, 2));
                tm1 = fmaxf(tm1, __shfl_xor_sync(0xffffffffu, tm1, 1));
                tm1 = fmaxf(tm1, __shfl_xor_sync(0xffffffffu, tm1, 2));

                const float mn0 = fmaxf(m0, tm0), mn1 = fmaxf(m1, tm1);
                const bool noup = (mn0 == m0) && (mn1 == m1);
                float c0 = 1.f, c1 = 1.f;
                if (!__all_sync(0xffffffffu, noup)) {
                    c0 = ex2f(m0 - mn0);
                    c1 = ex2f(m1 - mn1);
                    m0 = mn0; m1 = mn1;
                    #pragma unroll
                    for (int nt = 0; nt < 8; nt++) {
                        o[nt][0] *= c0; o[nt][1] *= c0;
                        o[nt][2] *= c1; o[nt][3] *= c1;
                    }
                }

                // ---- P = ex2(S-m) f16; row sums via MMA; O += P V ----
                float dsum[4] = {0.f, 0.f, 0.f, 0.f};
                #pragma unroll
                for (int kc = 0; kc < 4; kc++) {
                    const float* s0 = s[2 * kc];
                    const float* s1 = s[2 * kc + 1];
                    uint32_t ph[4];
                    ph[0] = ex2h2(packh2(s0[0] - m0, s0[1] - m0));
                    ph[1] = ex2h2(packh2(s0[2] - m1, s0[3] - m1));
                    ph[2] = ex2h2(packh2(s1[0] - m0, s1[1] - m0));
                    ph[3] = ex2h2(packh2(s1[2] - m1, s1[3] - m1));

                    mma_f16(dsum, ph, ONES2);

                    const int rowV = rVbase + kc * 16;
                    #pragma unroll
                    for (int nt16 = 0; nt16 < 4; nt16++) {
                        uint32_t vf[4];
                        ldm_x4_t(vf, stV + swz128(rowV, chV + nt16 * 2));
                        #pragma unroll
                        for (int hf = 0; hf < 2; hf++)
                            mma_f16(o[nt16 * 2 + hf], ph, &vf[hf * 2]);
                    }
                }
                l0 = l0 * c0 + dsum[0];
                l1 = l1 * c1 + dsum[2];
            }
        }
        cp_wait<0>();   // drain tail empties before ring reuse (next item)

        // ---- finalize: single f16 plane out ----
        const float inv0 = 1.f / l0, inv1 = 1.f / l1;

        const size_t row0 = (size_t)b * T_ + qb * 128 + wid * 16 + (lane >> 2);
        const size_t row1 = row0 + 8;
        const int colB = h * HD_ + (lane & 3) * 2;

        #pragma unroll
        for (int nt = 0; nt < 8; nt++) {
            const size_t i0 = row0 * D_ + colB + nt * 8;
            const size_t i1 = row1 * D_ + colB + nt * 8;
            reinterpret_cast<uint32_t*>(g_o16)[i0 >> 1] =
                packh2(o[nt][0] * inv0, o[nt][1] * inv0);
            reinterpret_cast<uint32_t*>(g_o16)[i1 >> 1] =
                packh2(o[nt][2] * inv1, o[nt][3] * inv1);
        }
    }
}

// ---------------------------------------------------------------------------
// Fused convert kernel: z in 0..3 -> transpose+quantize weight z;
// z == 4 -> quantize x (f32 -> f16, vectorized). Also resets tile counters.
// ---------------------------------------------------------------------------
__global__ __launch_bounds__(256) void convert_kernel(
    const float* __restrict__ wq, const float* __restrict__ wk,
    const float* __restrict__ wv, const float* __restrict__ wo,
    const float4* __restrict__ x)
{
    const int z = blockIdx.z;

    if (z == 4) {
        // x quant: 1024 blocks x 256 threads x 8 float4 = 8M floats
        const int bid  = blockIdx.y * 32 + blockIdx.x;
        const int base = bid * 256 + threadIdx.x;
        #pragma unroll
        for (int k = 0; k < 8; k++) {
            const int i = base + k * (1024 * 256);
            const float4 v = x[i];
            uint2 r;
            r.x = packh2(v.x, v.y);
            r.y = packh2(v.z, v.w);
            reinterpret_cast<uint2*>(g_x16)[i] = r;
        }
        return;
    }

    if (z == 0 && blockIdx.x == 0 && blockIdx.y == 0 && threadIdx.x == 0) {
        g_ctr[0] = 0;
        g_ctr[1] = 0;
        g_ctr[2] = 0;
    }

    __shared__ float tile[32][33];
    const float* w = (z == 0) ? wq : (z == 1) ? wk : (z == 2) ? wv : wo;
    const int nB = blockIdx.x * 32, kB = blockIdx.y * 32;
    const int tx = threadIdx.x & 31, ty = threadIdx.x >> 5;

    #pragma unroll
    for (int r = ty; r < 32; r += 8)
        tile[r][tx] = w[(size_t)(kB + r) * D_ + nB + tx];
    __syncthreads();
    #pragma unroll
    for (int r = ty; r < 32; r += 8) {
        const size_t di = ((size_t)z << 20) + (size_t)(nB + r) * D_ + kB + tx;
        g_wt[di] = __float2half_rn(tile[tx][r]);
    }
}

// ---------------------------------------------------------------------------
extern "C" void kernel_launch(void* const* d_in, const int* in_sizes, int n_in,
                              void* d_out, int out_size)
{
    const float* x  = (const float*)d_in[0];
    const float* wq = (const float*)d_in[1];
    const float* bq = (const float*)d_in[2];
    const float* wk = (const float*)d_in[3];
    const float* bk = (const float*)d_in[4];
    const float* wv = (const float*)d_in[5];
    const float* bv = (const float*)d_in[6];
    const float* wo = (const float*)d_in[7];
    const float* bo = (const float*)d_in[8];
    float* out = (float*)d_out;

    static bool attrSet = false;
    if (!attrSet) {
        cudaFuncSetAttribute(gemm_mma<0>,
                             cudaFuncAttributeMaxDynamicSharedMemorySize, GEMM_SMEM);
        cudaFuncSetAttribute(gemm_mma<1>,
                             cudaFuncAttributeMaxDynamicSharedMemorySize, GEMM_SMEM);
        cudaFuncSetAttribute(attn_mma,
                             cudaFuncAttributeMaxDynamicSharedMemorySize, ATT_SMEM);
        attrSet = true;
    }

    void *px16, *po16;
    cudaGetSymbolAddress(&px16, g_x16);
    cudaGetSymbolAddress(&po16, g_o16);

    // 1) converts (also resets the persistent counters)
    convert_kernel<<<dim3(32, 32, 5), 256>>>(wq, wk, wv, wo, (const float4*)x);

    // 2) QKV projections (persistent, 1536 tiles) -> q/k/v f16 [B,H,T,HD]
    gemm_mma<0><<<PERSIST_GRID, 256, GEMM_SMEM>>>(
        (const __half*)px16, bq, bk, bv, nullptr);

    // 3) persistent causal flash attention -> g_o16 [B*T, D]
    attn_mma<<<PERSIST_GRID, 256, ATT_SMEM>>>();

    // 4) output projection (persistent, 512 tiles)
    gemm_mma<1><<<PERSIST_GRID, 256, GEMM_SMEM>>>(
        (const __half*)po16, bo, nullptr, nullptr, out);
}

// round 17
// speedup vs baseline: 1.3221x; 1.0272x over previous
#include <cuda_runtime.h>
#include <cuda_fp16.h>
#include <cstdint>
#include <cstddef>

// ---------------------------------------------------------------------------
// Problem constants
// ---------------------------------------------------------------------------
constexpr int B_  = 4;
constexpr int T_  = 2048;
constexpr int D_  = 1024;
constexpr int H_  = 16;
constexpr int HD_ = 64;
constexpr int M_  = B_ * T_;   // 8192

constexpr float QSCALE = 0.18033688011112042f;  // 0.125 * log2(e)

constexpr int PERSIST_GRID = 304;               // 152 SMs x 2 CTAs

// ---------------------------------------------------------------------------
// Device scratch
// ---------------------------------------------------------------------------
__device__ __align__(128) __half g_x16[(size_t)M_ * D_];
__device__ __align__(128) __half g_o16[(size_t)M_ * D_];
__device__ __align__(128) __half g_q16[(size_t)M_ * D_];
__device__ __align__(128) __half g_k16[(size_t)M_ * D_];
__device__ __align__(128) __half g_v16[(size_t)M_ * D_];
__device__ __align__(128) __half g_wt[(size_t)4 * D_ * D_];
// work queues: 0=QKV tiles, 1=O tiles, 2=attention items
__device__ unsigned int g_ctr[3];
// readiness: g_qkvR[z*32 + b*8 + nblk] counts finished m-blocks (of 16)
__device__ unsigned int g_qkvR[96];
// g_oR[b*16 + qb] counts finished heads (of 16)
__device__ unsigned int g_oR[64];

// ---------------------------------------------------------------------------
// PTX helpers
// ---------------------------------------------------------------------------
__device__ __forceinline__ uint32_t smem_u32(const void* p) {
    uint32_t a;
    asm("{ .reg .u64 t; cvta.to.shared.u64 t, %1; cvt.u32.u64 %0, t; }"
        : "=r"(a) : "l"(p));
    return a;
}
__device__ __forceinline__ void cp16(uint32_t saddr, const void* gaddr) {
    asm volatile("cp.async.cg.shared.global [%0], [%1], 16;"
                 :: "r"(saddr), "l"(gaddr));
}
__device__ __forceinline__ void cp_commit() {
    asm volatile("cp.async.commit_group;");
}
template <int N>
__device__ __forceinline__ void cp_wait() {
    asm volatile("cp.async.wait_group %0;" :: "n"(N));
}
__device__ __forceinline__ void ldm_x4(uint32_t* r, uint32_t addr) {
    asm volatile("ldmatrix.sync.aligned.m8n8.x4.shared.b16 {%0,%1,%2,%3}, [%4];"
                 : "=r"(r[0]), "=r"(r[1]), "=r"(r[2]), "=r"(r[3]) : "r"(addr));
}
__device__ __forceinline__ void ldm_x4_t(uint32_t* r, uint32_t addr) {
    asm volatile("ldmatrix.sync.aligned.m8n8.x4.trans.shared.b16 {%0,%1,%2,%3}, [%4];"
                 : "=r"(r[0]), "=r"(r[1]), "=r"(r[2]), "=r"(r[3]) : "r"(addr));
}
__device__ __forceinline__ void mma_f16(float* c, const uint32_t* a,
                                        const uint32_t* b) {
    asm volatile(
        "mma.sync.aligned.m16n8k16.row.col.f32.f16.f16.f32 "
        "{%0,%1,%2,%3}, {%4,%5,%6,%7}, {%8,%9}, {%0,%1,%2,%3};"
        : "+f"(c[0]), "+f"(c[1]), "+f"(c[2]), "+f"(c[3])
        : "r"(a[0]), "r"(a[1]), "r"(a[2]), "r"(a[3]), "r"(b[0]), "r"(b[1]));
}
__device__ __forceinline__ float ex2f(float x) {
    float r;
    asm("ex2.approx.ftz.f32 %0, %1;" : "=f"(r) : "f"(x));
    return r;
}
__device__ __forceinline__ uint32_t packh2(float lo, float hi) {
    uint32_t r;
    asm("cvt.rn.f16x2.f32 %0, %1, %2;" : "=r"(r) : "f"(hi), "f"(lo));
    return r;
}
__device__ __forceinline__ uint32_t ex2h2(uint32_t x) {
    uint32_t r;
    asm("ex2.approx.f16x2 %0, %1;" : "=r"(r) : "r"(x));
    return r;
}
__device__ __forceinline__ uint32_t swz128(int row, int chunk) {
    return (uint32_t)row * 128u + (uint32_t)((chunk ^ (row & 7)) << 4);
}
__device__ __forceinline__ void spin_until(volatile unsigned int* p,
                                           unsigned int v) {
    while (*p < v) __nanosleep(128);
}

// ---------------------------------------------------------------------------
// Shared-memory geometry (identical for all phases)
// ---------------------------------------------------------------------------
constexpr int ARR_B    = 128 * 128;                 // 16384 B per 128x128B arr
constexpr int STAGE_B  = 2 * ARR_B;                 // 32768
constexpr int NSTG     = 3;
constexpr int SMEM_ALL = NSTG * STAGE_B + 128;      // ring + control slot
constexpr int KT_G     = D_ / 64;                   // 16 (BK=64)
constexpr int ATT_ITEMS = (T_ / 128) * H_ * B_;     // 1024

// ---------------------------------------------------------------------------
// Fused persistent kernel: QKV GEMM -> attention -> O GEMM, one launch.
// ---------------------------------------------------------------------------
__global__ __launch_bounds__(256, 2)
void fused_mha(const float* __restrict__ bq, const float* __restrict__ bk,
               const float* __restrict__ bv, const float* __restrict__ bo,
               float* __restrict__ out)
{
    extern __shared__ __align__(128) char smem[];
    const uint32_t sb = smem_u32(smem);
    int* slot = reinterpret_cast<int*>(smem + NSTG * STAGE_B);

    const int tid  = threadIdx.x;
    const int wid  = tid >> 5;
    const int lane = tid & 31;

    // =========================== Phase 1: QKV GEMM =========================
    {
        const int wm = (wid & 3) * 32;
        const int wn = (wid >> 2) * 64;
        int rowA[2], rowB[4];
        #pragma unroll
        for (int mi = 0; mi < 2; mi++)
            rowA[mi] = wm + (lane & 7) + ((lane >> 3) & 1) * 8 + mi * 16;
        #pragma unroll
        for (int p = 0; p < 4; p++)
            rowB[p] = wn + ((lane >> 4) & 1) * 8 + (lane & 7) + p * 16;
        const int chA = (lane >> 4) & 1;
        const int chB = (lane >> 3) & 1;

        for (;;) {
            __syncthreads();
            if (tid == 0)
                *slot = (int)atomicAdd(&g_ctr[0], 1u);
            __syncthreads();
            const int tile = *slot;
            if (tile >= 1536) break;

            // grouped (b, nblk)-major ordering: 48 tiles per group
            const int grp = tile / 48, idx = tile % 48;
            const int z = idx >> 4, mb16 = idx & 15;
            const int b = grp >> 3, nblk = grp & 7;
            const int mBase = (b * 16 + mb16) * 128;
            const int nBase = nblk * 128;
            const __half* A = g_x16;
            const __half* W = g_wt + ((size_t)z << 20);

            auto load_stage = [&](int stg, int kt) {
                const uint32_t st = sb + stg * STAGE_B;
                const int bk_ = kt * 64;
                #pragma unroll
                for (int j = 0; j < 4; j++) {
                    const int c = j * 256 + tid;
                    const int row = c >> 3, q8 = c & 7;
                    const uint32_t off = swz128(row, q8);
                    cp16(st + off, A + (size_t)(mBase + row) * D_ + bk_ + q8 * 8);
                    cp16(st + ARR_B + off,
                         W + (size_t)(nBase + row) * D_ + bk_ + q8 * 8);
                }
                cp_commit();
            };

            float acc[2][8][4];
            #pragma unroll
            for (int mi = 0; mi < 2; mi++)
                #pragma unroll
                for (int ni = 0; ni < 8; ni++)
                    #pragma unroll
                    for (int r = 0; r < 4; r++) acc[mi][ni][r] = 0.f;

            load_stage(0, 0);
            load_stage(1, 1);

            #pragma unroll 1
            for (int kt = 0; kt < KT_G; kt++) {
                cp_wait<1>();
                __syncthreads();
                if (kt + 2 < KT_G) load_stage((kt + 2) % NSTG, kt + 2);
                else               cp_commit();

                const uint32_t st = sb + (kt % NSTG) * STAGE_B;
                #pragma unroll
                for (int ks = 0; ks < 4; ks++) {
                    uint32_t af[2][4];
                    #pragma unroll
                    for (int mi = 0; mi < 2; mi++)
                        ldm_x4(af[mi], st + swz128(rowA[mi], chA + ks * 2));
                    uint32_t bf[4][4];
                    #pragma unroll
                    for (int p = 0; p < 4; p++)
                        ldm_x4(bf[p], st + ARR_B + swz128(rowB[p], chB + ks * 2));
                    #pragma unroll
                    for (int mi = 0; mi < 2; mi++)
                        #pragma unroll
                        for (int p = 0; p < 4; p++)
                            #pragma unroll
                            for (int hf = 0; hf < 2; hf++)
                                mma_f16(acc[mi][p * 2 + hf], af[mi],
                                        &bf[p][hf * 2]);
                }
            }
            cp_wait<0>();

            const float* bias = (z == 0) ? bq : (z == 1) ? bk : bv;
            __half* dst16 = (z == 0) ? g_q16 : (z == 1) ? g_k16 : g_v16;
            const float scale = (z == 0) ? QSCALE : 1.f;

            #pragma unroll
            for (int mi = 0; mi < 2; mi++) {
                #pragma unroll
                for (int ni = 0; ni < 8; ni++) {
                    const int n0 = nBase + wn + ni * 8 + (lane & 3) * 2;
                    const float bv0 = __ldg(bias + n0);
                    const float bv1 = __ldg(bias + n0 + 1);
                    #pragma unroll
                    for (int rr = 0; rr < 2; rr++) {
                        const int m = mBase + wm + mi * 16 + (lane >> 2) + rr * 8;
                        const float v0 = (acc[mi][ni][rr * 2 + 0] + bv0) * scale;
                        const float v1 = (acc[mi][ni][rr * 2 + 1] + bv1) * scale;
                        const int bb = m >> 11, tt = m & 2047;
                        const int hh = n0 >> 6, hd = n0 & 63;
                        const size_t dI =
                            ((((size_t)bb * H_ + hh) * T_ + tt) << 6) + hd;
                        reinterpret_cast<uint32_t*>(dst16)[dI >> 1] =
                            packh2(v0, v1);
                    }
                }
            }

            __syncthreads();
            __threadfence();
            if (tid == 0)
                atomicAdd(&g_qkvR[z * 32 + b * 8 + nblk], 1u);
        }
    }

    // =========================== Phase 2: attention ========================
    {
        const int rKbase = ((lane >> 4) & 1) * 8 + (lane & 7);
        const int chK    = (lane >> 3) & 1;
        const int rVbase = (lane & 7) + ((lane >> 3) & 1) * 8;
        const int chV    = (lane >> 4) & 1;
        const uint32_t ONES2[2] = {0x3C003C00u, 0x3C003C00u};

        for (;;) {
            __syncthreads();
            if (tid == 0)
                *slot = (int)atomicAdd(&g_ctr[2], 1u);
            __syncthreads();
            const int item = *slot;
            if (item >= ATT_ITEMS) break;

            const int qb   = (T_ / 128 - 1) - (item >> 6);
            const int bhid = item & 63;
            const int b    = bhid >> 4;
            const int h    = bhid & 15;
            const size_t bh = ((size_t)(b * H_ + h)) * T_ * HD_;

            // wait for q/k/v of this (b, head-pair) to be fully written
            if (tid == 0) {
                const int rb = b * 8 + (h >> 1);
                spin_until(&g_qkvR[rb], 16u);           // z=0 (q)
                spin_until(&g_qkvR[32 + rb], 16u);      // z=1 (k)
                spin_until(&g_qkvR[64 + rb], 16u);      // z=2 (v)
                __threadfence();
            }
            __syncthreads();

            const __half* Q = g_q16 + bh + (size_t)qb * 128 * HD_;
            const __half* K = g_k16 + bh;
            const __half* V = g_v16 + bh;
            const int KT = qb + 1;       // 128-key tiles

            // Q via ring stage 0
            #pragma unroll
            for (int i = 0; i < 4; i++) {
                const int c = i * 256 + tid;
                const int row = c >> 3, q8 = c & 7;
                cp16(sb + swz128(row, q8), Q + (size_t)row * HD_ + q8 * 8);
            }
            cp_commit();
            cp_wait<0>();
            __syncthreads();

            uint32_t qf[4][4];
            {
                const int rowQ = wid * 16 + (lane & 7) + ((lane >> 3) & 1) * 8;
                const int chQ  = (lane >> 4) & 1;
                #pragma unroll
                for (int kc = 0; kc < 4; kc++)
                    ldm_x4(qf[kc], sb + swz128(rowQ, chQ + kc * 2));
            }
            __syncthreads();

            auto load_kv = [&](int stg, int kt) {
                const uint32_t base = sb + stg * STAGE_B;
                #pragma unroll
                for (int i = 0; i < 8; i++) {
                    const int c = i * 256 + tid;
                    const int arr = c >> 10, row = (c >> 3) & 127, q8 = c & 7;
                    const __half* g = arr ? V : K;
                    cp16(base + arr * ARR_B + swz128(row, q8),
                         g + (size_t)(kt * 128 + row) * HD_ + q8 * 8);
                }
                cp_commit();
            };
            #pragma unroll
            for (int j = 0; j < 2; j++) {
                if (j < KT) load_kv(j, j);
                else        cp_commit();
            }

            float o[8][4];
            #pragma unroll
            for (int nt = 0; nt < 8; nt++)
                #pragma unroll
                for (int r = 0; r < 4; r++) o[nt][r] = 0.f;
            float m0 = -1e30f, m1 = -1e30f, l0 = 0.f, l1 = 0.f;

            const int r0g = qb * 128 + wid * 16 + (lane >> 2);

            #pragma unroll 1
            for (int kt = 0; kt < KT; kt++) {
                cp_wait<1>();
                __syncthreads();
                if (kt + 2 < KT) load_kv((kt + 2) % NSTG, kt + 2);
                else             cp_commit();

                const uint32_t st = sb + (kt % NSTG) * STAGE_B;
                const bool diag = (kt == KT - 1);

                #pragma unroll
                for (int half = 0; half < 2; half++) {
                    const uint32_t stK = st + half * (ARR_B / 2);
                    const uint32_t stV = st + ARR_B + half * (ARR_B / 2);

                    float s[8][4];
                    #pragma unroll
                    for (int nt = 0; nt < 8; nt++)
                        #pragma unroll
                        for (int r = 0; r < 4; r++) s[nt][r] = 0.f;

                    #pragma unroll
                    for (int kc = 0; kc < 4; kc++) {
                        #pragma unroll
                        for (int g = 0; g < 2; g++) {
                            uint32_t kf[2][4];
                            #pragma unroll
                            for (int t = 0; t < 2; t++) {
                                const int nt16 = g * 2 + t;
                                ldm_x4(kf[t], stK + swz128(rKbase + nt16 * 16,
                                                           chK + kc * 2));
                            }
                            #pragma unroll
                            for (int t = 0; t < 2; t++)
                                #pragma unroll
                                for (int hf = 0; hf < 2; hf++)
                                    mma_f16(s[(g * 2 + t) * 2 + hf], qf[kc],
                                            &kf[t][hf * 2]);
                        }
                    }

                    if (diag) {
                        const int colBase = kt * 128 + half * 64 + (lane & 3) * 2;
                        #pragma unroll
                        for (int nt = 0; nt < 8; nt++)
                            #pragma unroll
                            for (int j = 0; j < 2; j++) {
                                const int c = colBase + nt * 8 + j;
                                if (c > r0g)     s[nt][j]     = -30000.f;
                                if (c > r0g + 8) s[nt][2 + j] = -30000.f;
                            }
                    }

                    float tm0 = -1e30f, tm1 = -1e30f;
                    #pragma unroll
                    for (int nt = 0; nt < 8; nt++) {
                        tm0 = fmaxf(tm0, fmaxf(s[nt][0], s[nt][1]));
                        tm1 = fmaxf(tm1, fmaxf(s[nt][2], s[nt][3]));
                    }
                    tm0 = fmaxf(tm0, __shfl_xor_sync(0xffffffffu, tm0, 1));
                    tm0 = fmaxf(tm0, __shfl_xor_sync(0xffffffffu, tm0, 2));
                    tm1 = fmaxf(tm1, __shfl_xor_sync(0xffffffffu, tm1, 1));
                    tm1 = fmaxf(tm1, __shfl_xor_sync(0xffffffffu, tm1, 2));

                    const float mn0 = fmaxf(m0, tm0), mn1 = fmaxf(m1, tm1);
                    const bool noup = (mn0 == m0) && (mn1 == m1);
                    float c0 = 1.f, c1 = 1.f;
                    if (!__all_sync(0xffffffffu, noup)) {
                        c0 = ex2f(m0 - mn0);
                        c1 = ex2f(m1 - mn1);
                        m0 = mn0; m1 = mn1;
                        #pragma unroll
                        for (int nt = 0; nt < 8; nt++) {
                            o[nt][0] *= c0; o[nt][1] *= c0;
                            o[nt][2] *= c1; o[nt][3] *= c1;
                        }
                    }

                    float dsum[4] = {0.f, 0.f, 0.f, 0.f};
                    #pragma unroll
                    for (int kc = 0; kc < 4; kc++) {
                        const float* s0 = s[2 * kc];
                        const float* s1 = s[2 * kc + 1];
                        uint32_t ph[4];
                        ph[0] = ex2h2(packh2(s0[0] - m0, s0[1] - m0));
                        ph[1] = ex2h2(packh2(s0[2] - m1, s0[3] - m1));
                        ph[2] = ex2h2(packh2(s1[0] - m0, s1[1] - m0));
                        ph[3] = ex2h2(packh2(s1[2] - m1, s1[3] - m1));

                        mma_f16(dsum, ph, ONES2);

                        const int rowV = rVbase + kc * 16;
                        #pragma unroll
                        for (int nt16 = 0; nt16 < 4; nt16++) {
                            uint32_t vf[4];
                            ldm_x4_t(vf, stV + swz128(rowV, chV + nt16 * 2));
                            #pragma unroll
                            for (int hf = 0; hf < 2; hf++)
                                mma_f16(o[nt16 * 2 + hf], ph, &vf[hf * 2]);
                        }
                    }
                    l0 = l0 * c0 + dsum[0];
                    l1 = l1 * c1 + dsum[2];
                }
            }
            cp_wait<0>();

            const float inv0 = 1.f / l0, inv1 = 1.f / l1;
            const size_t row0 =
                (size_t)b * T_ + qb * 128 + wid * 16 + (lane >> 2);
            const size_t row1 = row0 + 8;
            const int colB = h * HD_ + (lane & 3) * 2;

            #pragma unroll
            for (int nt = 0; nt < 8; nt++) {
                const size_t i0 = row0 * D_ + colB + nt * 8;
                const size_t i1 = row1 * D_ + colB + nt * 8;
                reinterpret_cast<uint32_t*>(g_o16)[i0 >> 1] =
                    packh2(o[nt][0] * inv0, o[nt][1] * inv0);
                reinterpret_cast<uint32_t*>(g_o16)[i1 >> 1] =
                    packh2(o[nt][2] * inv1, o[nt][3] * inv1);
            }

            __syncthreads();
            __threadfence();
            if (tid == 0)
                atomicAdd(&g_oR[b * 16 + qb], 1u);
        }
    }

    // =========================== Phase 3: O GEMM ===========================
    {
        const int wm = (wid & 3) * 32;
        const int wn = (wid >> 2) * 64;
        int rowA[2], rowB[4];
        #pragma unroll
        for (int mi = 0; mi < 2; mi++)
            rowA[mi] = wm + (lane & 7) + ((lane >> 3) & 1) * 8 + mi * 16;
        #pragma unroll
        for (int p = 0; p < 4; p++)
            rowB[p] = wn + ((lane >> 4) & 1) * 8 + (lane & 7) + p * 16;
        const int chA = (lane >> 4) & 1;
        const int chB = (lane >> 3) & 1;

        const __half* A = g_o16;
        const __half* W = g_wt + ((size_t)3 << 20);

        for (;;) {
            __syncthreads();
            if (tid == 0)
                *slot = (int)atomicAdd(&g_ctr[1], 1u);
            __syncthreads();
            const int tile = *slot;
            if (tile >= 512) break;

            const int mBase = (tile >> 3) * 128;
            const int nBase = (tile & 7) * 128;

            // wait until all 16 heads of this (b, qb) row-block are written
            if (tid == 0) {
                spin_until(&g_oR[mBase >> 7], 16u);   // (b*16 + qb)
                __threadfence();
            }
            __syncthreads();

            auto load_stage = [&](int stg, int kt) {
                const uint32_t st = sb + stg * STAGE_B;
                const int bk_ = kt * 64;
                #pragma unroll
                for (int j = 0; j < 4; j++) {
                    const int c = j * 256 + tid;
                    const int row = c >> 3, q8 = c & 7;
                    const uint32_t off = swz128(row, q8);
                    cp16(st + off, A + (size_t)(mBase + row) * D_ + bk_ + q8 * 8);
                    cp16(st + ARR_B + off,
                         W + (size_t)(nBase + row) * D_ + bk_ + q8 * 8);
                }
                cp_commit();
            };

            float acc[2][8][4];
            #pragma unroll
            for (int mi = 0; mi < 2; mi++)
                #pragma unroll
                for (int ni = 0; ni < 8; ni++)
                    #pragma unroll
                    for (int r = 0; r < 4; r++) acc[mi][ni][r] = 0.f;

            load_stage(0, 0);
            load_stage(1, 1);

            #pragma unroll 1
            for (int kt = 0; kt < KT_G; kt++) {
                cp_wait<1>();
                __syncthreads();
                if (kt + 2 < KT_G) load_stage((kt + 2) % NSTG, kt + 2);
                else               cp_commit();

                const uint32_t st = sb + (kt % NSTG) * STAGE_B;
                #pragma unroll
                for (int ks = 0; ks < 4; ks++) {
                    uint32_t af[2][4];
                    #pragma unroll
                    for (int mi = 0; mi < 2; mi++)
                        ldm_x4(af[mi], st + swz128(rowA[mi], chA + ks * 2));
                    uint32_t bf[4][4];
                    #pragma unroll
                    for (int p = 0; p < 4; p++)
                        ldm_x4(bf[p], st + ARR_B + swz128(rowB[p], chB + ks * 2));
                    #pragma unroll
                    for (int mi = 0; mi < 2; mi++)
                        #pragma unroll
                        for (int p = 0; p < 4; p++)
                            #pragma unroll
                            for (int hf = 0; hf < 2; hf++)
                                mma_f16(acc[mi][p * 2 + hf], af[mi],
                                        &bf[p][hf * 2]);
                }
            }
            cp_wait<0>();

            #pragma unroll
            for (int mi = 0; mi < 2; mi++) {
                #pragma unroll
                for (int ni = 0; ni < 8; ni++) {
                    const int n0 = nBase + wn + ni * 8 + (lane & 3) * 2;
                    const float bv0 = __ldg(bo + n0);
                    const float bv1 = __ldg(bo + n0 + 1);
                    #pragma unroll
                    for (int rr = 0; rr < 2; rr++) {
                        const int m = mBase + wm + mi * 16 + (lane >> 2) + rr * 8;
                        *reinterpret_cast<float2*>(out + (size_t)m * D_ + n0) =
                            make_float2(acc[mi][ni][rr * 2 + 0] + bv0,
                                        acc[mi][ni][rr * 2 + 1] + bv1);
                    }
                }
            }
        }
    }
}

// ---------------------------------------------------------------------------
// Fused convert kernel: z in 0..3 -> transpose+quantize weight z;
// z == 4 -> quantize x. Also resets all queue/readiness counters.
// ---------------------------------------------------------------------------
__global__ __launch_bounds__(256) void convert_kernel(
    const float* __restrict__ wq, const float* __restrict__ wk,
    const float* __restrict__ wv, const float* __restrict__ wo,
    const float4* __restrict__ x)
{
    const int z = blockIdx.z;

    if (z == 4) {
        const int bid  = blockIdx.y * 32 + blockIdx.x;
        const int base = bid * 256 + threadIdx.x;
        #pragma unroll
        for (int k = 0; k < 8; k++) {
            const int i = base + k * (1024 * 256);
            const float4 v = x[i];
            uint2 r;
            r.x = packh2(v.x, v.y);
            r.y = packh2(v.z, v.w);
            reinterpret_cast<uint2*>(g_x16)[i] = r;
        }
        return;
    }

    if (z == 0 && blockIdx.x == 0 && blockIdx.y == 0) {
        if (threadIdx.x < 3)   g_ctr[threadIdx.x] = 0;
        if (threadIdx.x < 96)  g_qkvR[threadIdx.x] = 0;
        if (threadIdx.x >= 96 && threadIdx.x < 160)
            g_oR[threadIdx.x - 96] = 0;
    }

    __shared__ float tile[32][33];
    const float* w = (z == 0) ? wq : (z == 1) ? wk : (z == 2) ? wv : wo;
    const int nB = blockIdx.x * 32, kB = blockIdx.y * 32;
    const int tx = threadIdx.x & 31, ty = threadIdx.x >> 5;

    #pragma unroll
    for (int r = ty; r < 32; r += 8)
        tile[r][tx] = w[(size_t)(kB + r) * D_ + nB + tx];
    __syncthreads();
    #pragma unroll
    for (int r = ty; r < 32; r += 8) {
        const size_t di = ((size_t)z << 20) + (size_t)(nB + r) * D_ + kB + tx;
        g_wt[di] = __float2half_rn(tile[tx][r]);
    }
}

// ---------------------------------------------------------------------------
extern "C" void kernel_launch(void* const* d_in, const int* in_sizes, int n_in,
                              void* d_out, int out_size)
{
    const float* x  = (const float*)d_in[0];
    const float* wq = (const float*)d_in[1];
    const float* bq = (const float*)d_in[2];
    const float* wk = (const float*)d_in[3];
    const float* bk = (const float*)d_in[4];
    const float* wv = (const float*)d_in[5];
    const float* bv = (const float*)d_in[6];
    const float* wo = (const float*)d_in[7];
    const float* bo = (const float*)d_in[8];
    float* out = (float*)d_out;

    static bool attrSet = false;
    if (!attrSet) {
        cudaFuncSetAttribute(fused_mha,
                             cudaFuncAttributeMaxDynamicSharedMemorySize,
                             SMEM_ALL);
        attrSet = true;
    }

    // 1) converts + counter reset
    convert_kernel<<<dim3(32, 32, 5), 256>>>(wq, wk, wv, wo, (const float4*)x);

    // 2) fused persistent QKV -> attention -> O projection
    fused_mha<<<PERSIST_GRID, 256, SMEM_ALL>>>(bq, bk, bv, bo, out);
}